// round 1
// baseline (speedup 1.0000x reference)
#include <cuda_runtime.h>

// Problem constants (fixed by the dataset)
#define T_STEPS 8
#define NN      100000
#define EE      1600000
#define FLAT    4096    // 64*64
#define BN      1024    // bottleneck

// ---------------- device scratch (no allocs allowed) ----------------
__device__ float  g_w[FLAT];
__device__ float  g_ws[FLAT];
__device__ float  g_k1[FLAT];
__device__ float  g_k2[FLAT];
__device__ float  g_k3[FLAT];
__device__ float  g_t[BN];
__device__ float  g_dis[NN];
__device__ float4 g_z4[NN * 16];    // dis[n] * (x W_T)   [N,64]
__device__ float4 g_acc4[NN * 16];  // scatter accumulator [N,64]
__device__ float4 g_hA4[NN * 16];   // h @ A + b1          [N,64]
__device__ float4 g_hB4[NN * 16];   // h @ B               [N,64]

// ---------------- init: copy w0, deg := 1 (self loop) ----------------
__global__ void init_kernel(const float* __restrict__ iw, int n) {
    int i = blockIdx.x * 256 + threadIdx.x;
    if (i < FLAT) g_w[i] = iw[i];
    if (i < n)    g_dis[i] = 1.0f;
}

// ---------------- degree scatter ----------------
__global__ void deg_kernel(const int* __restrict__ ei, int e) {
    int i = blockIdx.x * 256 + threadIdx.x;
    if (i < e) atomicAdd(&g_dis[ei[e + i]], 1.0f);
}

__global__ void rsqrt_kernel(int n) {
    int i = blockIdx.x * 256 + threadIdx.x;
    if (i < n) g_dis[i] = rsqrtf(g_dis[i]);
}

// ---------------- ODE layer 1: t = tanh(win @ W1 + b1), t in [1024] ----------------
// grid 128 blocks x 256 threads; block b computes outputs j in [8b, 8b+8)
__global__ void ode_l1(const float* __restrict__ W1, const float* __restrict__ b1,
                       int use_ws) {
    const float* __restrict__ win = use_ws ? g_ws : g_w;
    int jl = threadIdx.x & 7;        // output within block
    int kg = threadIdx.x >> 3;       // k group 0..31
    int j  = blockIdx.x * 8 + jl;
    float s = 0.f;
#pragma unroll 8
    for (int k = kg; k < FLAT; k += 32)
        s += win[k] * W1[k * BN + j];
    // reduce the 4 kg values that live in this warp (lanes differ by 8,16)
    s += __shfl_xor_sync(0xffffffffu, s, 8);
    s += __shfl_xor_sync(0xffffffffu, s, 16);
    __shared__ float red[8][8];
    int warp = threadIdx.x >> 5, lane = threadIdx.x & 31;
    if (lane < 8) red[warp][lane] = s;
    __syncthreads();
    if (threadIdx.x < 8) {
        float tot = 0.f;
#pragma unroll
        for (int w = 0; w < 8; ++w) tot += red[w][threadIdx.x];
        int jj = blockIdx.x * 8 + threadIdx.x;
        g_t[jj] = tanhf(tot + b1[jj]);
    }
}

// ---------------- ODE layer 2 + fused RK4 stage update ----------------
// grid 128 blocks x 256 threads; block b computes outputs j in [32b, 32b+32)
__global__ void ode_l2e(const float* __restrict__ W2, const float* __restrict__ b2,
                        int stage, float h) {
    __shared__ float ts[BN];
    __shared__ float red[8][32];
    for (int i = threadIdx.x; i < BN; i += 256) ts[i] = g_t[i];
    __syncthreads();
    int jl = threadIdx.x & 31;
    int kg = threadIdx.x >> 5;       // == warp id
    int j  = blockIdx.x * 32 + jl;
    float s = 0.f;
#pragma unroll 8
    for (int k = kg; k < BN; k += 8)
        s += ts[k] * W2[k * FLAT + j];
    red[kg][jl] = s;
    __syncthreads();
    if (threadIdx.x < 32) {
        float z = 0.f;
#pragma unroll
        for (int w = 0; w < 8; ++w) z += red[w][threadIdx.x];
        int jj = blockIdx.x * 32 + threadIdx.x;
        z += b2[jj];
        float w0 = g_w[jj];
        if (stage == 0) {
            g_k1[jj] = z;
            g_ws[jj] = w0 + (h * (1.f / 3.f)) * z;
        } else if (stage == 1) {
            g_k2[jj] = z;
            g_ws[jj] = w0 + h * (z - g_k1[jj] * (1.f / 3.f));
        } else if (stage == 2) {
            g_k3[jj] = z;
            g_ws[jj] = w0 + h * (g_k1[jj] - g_k2[jj] + z);
        } else {
            g_w[jj] = w0 + h * 0.125f * (g_k1[jj] + 3.f * (g_k2[jj] + g_k3[jj]) + z);
        }
    }
}

// ---------------- xw: z[n] = dis[n] * (x_last[n] @ W_T); acc[n] = dis[n]*z[n] ----------------
// block: 256 threads as 16x16, each thread computes a 4x4 micro-tile of a 64x64 block
__global__ void xw_kernel(const float* __restrict__ xlast, int n) {
    __shared__ float Ws[64 * 64];
    __shared__ float xs[64 * 64];
    int n0 = blockIdx.x * 64;
    for (int i = threadIdx.x; i < 4096; i += 256) Ws[i] = g_w[i];
    for (int i = threadIdx.x; i < 4096; i += 256) {
        int r = i >> 6, c = i & 63, nn = n0 + r;
        xs[i] = (nn < n) ? xlast[(size_t)nn * 64 + c] : 0.f;
    }
    __syncthreads();
    int tx = threadIdx.x & 15, ty = threadIdx.x >> 4;
    float acc[4][4] = {};
#pragma unroll 4
    for (int k = 0; k < 64; ++k) {
        float4 b = *(const float4*)&Ws[k * 64 + tx * 4];
#pragma unroll
        for (int i = 0; i < 4; ++i) {
            float a = xs[(ty * 4 + i) * 64 + k];
            acc[i][0] += a * b.x; acc[i][1] += a * b.y;
            acc[i][2] += a * b.z; acc[i][3] += a * b.w;
        }
    }
    float* gz = (float*)g_z4;
    float* ga = (float*)g_acc4;
#pragma unroll
    for (int i = 0; i < 4; ++i) {
        int nn = n0 + ty * 4 + i;
        if (nn < n) {
            float dn = g_dis[nn];
            float4 z, a2;
            z.x = dn * acc[i][0]; z.y = dn * acc[i][1];
            z.z = dn * acc[i][2]; z.w = dn * acc[i][3];
            a2.x = dn * z.x; a2.y = dn * z.y; a2.z = dn * z.z; a2.w = dn * z.w;
            *(float4*)&gz[nn * 64 + tx * 4] = z;   // edge gather table
            *(float4*)&ga[nn * 64 + tx * 4] = a2;  // self-loop term = accumulator init
        }
    }
}

// ---------------- scatter: acc[col] += dis[col] * z[row], vec4 reductions ----------------
__global__ void scatter_kernel(const int* __restrict__ ei, int e) {
    int idx = blockIdx.x * 256 + threadIdx.x;
    if (idx >= e * 16) return;
    int eg = idx >> 4, q = idx & 15;
    int r = __ldg(&ei[eg]);
    int c = __ldg(&ei[e + eg]);
    float dc = g_dis[c];
    float4 v = g_z4[r * 16 + q];
    v.x *= dc; v.y *= dc; v.z *= dc; v.w *= dc;
    float4* p = &g_acc4[c * 16 + q];
    asm volatile("red.global.add.v4.f32 [%0], {%1, %2, %3, %4};"
                 :: "l"(p), "f"(v.x), "f"(v.y), "f"(v.z), "f"(v.w) : "memory");
}

// ---------------- hA/hB: h = relu(acc); hA = h@W[0:64]+b1; hB = h@W[64:128] ----------------
__global__ void hab_kernel(const float* __restrict__ mw1, const float* __restrict__ mb1,
                           int n) {
    int sel = blockIdx.y;  // 0 -> A (+bias), 1 -> B
    __shared__ float Ws[64 * 64];
    __shared__ float xs[64 * 64];
    const float* ga = (const float*)g_acc4;
    int n0 = blockIdx.x * 64;
    for (int i = threadIdx.x; i < 4096; i += 256) Ws[i] = mw1[sel * 4096 + i];
    for (int i = threadIdx.x; i < 4096; i += 256) {
        int r = i >> 6, c = i & 63, nn = n0 + r;
        xs[i] = (nn < n) ? fmaxf(ga[nn * 64 + c], 0.f) : 0.f;
    }
    __syncthreads();
    int tx = threadIdx.x & 15, ty = threadIdx.x >> 4;
    float acc[4][4] = {};
#pragma unroll 4
    for (int k = 0; k < 64; ++k) {
        float4 b = *(const float4*)&Ws[k * 64 + tx * 4];
#pragma unroll
        for (int i = 0; i < 4; ++i) {
            float a = xs[(ty * 4 + i) * 64 + k];
            acc[i][0] += a * b.x; acc[i][1] += a * b.y;
            acc[i][2] += a * b.z; acc[i][3] += a * b.w;
        }
    }
    float4 bb = make_float4(0.f, 0.f, 0.f, 0.f);
    if (sel == 0) {
        bb.x = mb1[tx * 4 + 0]; bb.y = mb1[tx * 4 + 1];
        bb.z = mb1[tx * 4 + 2]; bb.w = mb1[tx * 4 + 3];
    }
    float* out = sel ? (float*)g_hB4 : (float*)g_hA4;
#pragma unroll
    for (int i = 0; i < 4; ++i) {
        int nn = n0 + ty * 4 + i;
        if (nn < n) {
            float4 v;
            v.x = acc[i][0] + bb.x; v.y = acc[i][1] + bb.y;
            v.z = acc[i][2] + bb.z; v.w = acc[i][3] + bb.w;
            *(float4*)&out[nn * 64 + tx * 4] = v;
        }
    }
}

// ---------------- edge MLP: out[e] = relu(hA[r]+hB[c]+ea@C) . w2 + b2 ----------------
// warp per edge; C (16x64) + w2 in smem; ea broadcast via shuffles
__global__ void edge_kernel(const float* __restrict__ ea, const int* __restrict__ ei,
                            const float* __restrict__ mw1, const float* __restrict__ w2,
                            const float* __restrict__ b2, float* __restrict__ out, int e) {
    __shared__ float Cs[16 * 64];
    __shared__ float w2s[64];
    for (int i = threadIdx.x; i < 1024; i += 256) Cs[i] = mw1[128 * 64 + i];
    if (threadIdx.x < 64) w2s[threadIdx.x] = w2[threadIdx.x];
    __syncthreads();
    int warp = threadIdx.x >> 5, lane = threadIdx.x & 31;
    int eg = blockIdx.x * 8 + warp;
    if (eg >= e) return;
    const float* hA = (const float*)g_hA4;
    const float* hB = (const float*)g_hB4;
    int r = __ldg(&ei[eg]);
    int c = __ldg(&ei[e + eg]);
    float av = (lane < 16) ? __ldg(&ea[(size_t)eg * 16 + lane]) : 0.f;
    int j0 = lane, j1 = lane + 32;
    float s0 = hA[r * 64 + j0] + hB[c * 64 + j0];
    float s1 = hA[r * 64 + j1] + hB[c * 64 + j1];
#pragma unroll
    for (int f = 0; f < 16; ++f) {
        float a = __shfl_sync(0xffffffffu, av, f);
        s0 += a * Cs[f * 64 + j0];
        s1 += a * Cs[f * 64 + j1];
    }
    float p = fmaxf(s0, 0.f) * w2s[j0] + fmaxf(s1, 0.f) * w2s[j1];
#pragma unroll
    for (int o = 16; o; o >>= 1) p += __shfl_xor_sync(0xffffffffu, p, o);
    if (lane == 0) out[eg] = p + b2[0];
}

// ---------------- launcher ----------------
extern "C" void kernel_launch(void* const* d_in, const int* in_sizes, int n_in,
                              void* d_out, int out_size) {
    const float* x_seq = (const float*)d_in[0];
    const float* ea    = (const float*)d_in[1];
    const float* iw    = (const float*)d_in[2];
    const float* W1    = (const float*)d_in[3];
    const float* b1o   = (const float*)d_in[4];
    const float* W2    = (const float*)d_in[5];
    const float* b2o   = (const float*)d_in[6];
    const float* mw1   = (const float*)d_in[7];
    const float* mb1   = (const float*)d_in[8];
    const float* mw2   = (const float*)d_in[9];
    const float* mb2   = (const float*)d_in[10];
    const int*   ei    = (const int*)d_in[11];
    float* out = (float*)d_out;

    const int n = NN;
    const int e = EE;
    const float* xlast = x_seq + (size_t)(T_STEPS - 1) * n * 64;
    const float h = 1.0f / (float)(T_STEPS - 1);

    // degree / normalization (independent of ODE)
    init_kernel<<<(n + 255) / 256, 256>>>(iw, n);
    deg_kernel<<<(e + 255) / 256, 256>>>(ei, e);
    rsqrt_kernel<<<(n + 255) / 256, 256>>>(n);

    // weight ODE: 7 steps x 4 RK4-alt stages
    for (int s = 0; s < T_STEPS - 1; ++s) {
        for (int st = 0; st < 4; ++st) {
            ode_l1<<<128, 256>>>(W1, b1o, st == 0 ? 0 : 1);
            ode_l2e<<<128, 256>>>(W2, b2o, st, h);
        }
    }

    // GCN
    xw_kernel<<<(n + 63) / 64, 256>>>(xlast, n);
    scatter_kernel<<<(e * 16 + 255) / 256, 256>>>(ei, e);

    // node-side halves of the edge MLP first layer
    dim3 hg((n + 63) / 64, 2);
    hab_kernel<<<hg, 256>>>(mw1, mb1, n);

    // per-edge MLP
    edge_kernel<<<(e + 7) / 8, 256>>>(ea, ei, mw1, mw2, mb2, out, e);
}

// round 2
// speedup vs baseline: 1.1112x; 1.1112x over previous
#include <cuda_runtime.h>

// Problem constants (fixed by the dataset)
#define T_STEPS 8
#define NN      100000
#define EE      1600000
#define FLAT    4096    // 64*64
#define BN      1024    // bottleneck
#define NB_ODE  128     // persistent ODE grid (<= SM count, co-resident)

// ---------------- device scratch (no allocs allowed) ----------------
__device__ float  g_w[FLAT];
__device__ float  g_ws[FLAT];
__device__ float  g_t[BN];
__device__ float  g_W1t[BN * FLAT];   // transposed: row j (1024 rows) x k (4096)
__device__ float  g_W2t[FLAT * BN];   // transposed: row j (4096 rows) x k (1024)
__device__ unsigned g_barcnt;
__device__ unsigned g_bargen;
__device__ float  g_dis[NN];
__device__ float4 g_z4[NN * 16];    // dis[n] * (x W_T)   [N,64]
__device__ float4 g_acc4[NN * 16];  // scatter accumulator [N,64]
__device__ float4 g_hA4[NN * 16];   // h @ A + b1          [N,64]
__device__ float4 g_hB4[NN * 16];   // h @ B               [N,64]

// ---------------- init: copy w0, deg := 1 (self loop) ----------------
__global__ void init_kernel(const float* __restrict__ iw, int n) {
    int i = blockIdx.x * 256 + threadIdx.x;
    if (i < FLAT) g_w[i] = iw[i];
    if (i < n)    g_dis[i] = 1.0f;
}

// ---------------- degree scatter ----------------
__global__ void deg_kernel(const int* __restrict__ ei, int e) {
    int i = blockIdx.x * 256 + threadIdx.x;
    if (i < e) atomicAdd(&g_dis[ei[e + i]], 1.0f);
}

__global__ void rsqrt_kernel(int n) {
    int i = blockIdx.x * 256 + threadIdx.x;
    if (i < n) g_dis[i] = rsqrtf(g_dis[i]);
}

// ---------------- 32x32 tiled transpose: dst[C][R] = src[R][C]^T ----------------
__global__ void transpose_kernel(const float* __restrict__ src, float* __restrict__ dst,
                                 int R, int C) {
    __shared__ float tile[32][33];
    int bx = blockIdx.x * 32, by = blockIdx.y * 32;
    int x = bx + threadIdx.x;
#pragma unroll
    for (int i = 0; i < 32; i += 8) {
        int y = by + threadIdx.y + i;
        tile[threadIdx.y + i][threadIdx.x] = src[(size_t)y * C + x];
    }
    __syncthreads();
    int x2 = by + threadIdx.x;
#pragma unroll
    for (int i = 0; i < 32; i += 8) {
        int y2 = bx + threadIdx.y + i;
        dst[(size_t)y2 * R + x2] = tile[threadIdx.x][threadIdx.y + i];
    }
}

// ---------------- persistent ODE: all 7 steps x 4 stages in one kernel ----------------
__device__ __forceinline__ void gridsync() {
    __syncthreads();
    if (threadIdx.x == 0) {
        __threadfence();
        unsigned gen = *(volatile unsigned*)&g_bargen;
        if (atomicAdd(&g_barcnt, 1u) == NB_ODE - 1) {
            g_barcnt = 0;
            __threadfence();
            *(volatile unsigned*)&g_bargen = gen + 1;
        } else {
            while (*(volatile unsigned*)&g_bargen == gen) __nanosleep(64);
        }
        __threadfence();
    }
    __syncthreads();
}

__global__ __launch_bounds__(1024, 1)
void ode_persist(const float* __restrict__ b1, const float* __restrict__ b2, float h) {
    __shared__ __align__(16) float sw[FLAT];   // current w-stage vector (16KB)
    __shared__ __align__(16) float st[BN];     // tanh activations (4KB)
    __shared__ float redA[8][4];

    const int tid  = threadIdx.x;
    const int grp  = tid >> 7;        // 0..7   : output group for layer 1
    const int tin  = tid & 127;       // 0..127
    const int wgrp = tin >> 5;        // warp within group 0..3
    const int wid  = tid >> 5;        // 0..31  : warp id -> layer-2 output
    const int lane = tid & 31;

    const int j1 = blockIdx.x * 8 + grp;              // layer-1 output (0..1023)
    const int j2 = blockIdx.x * 32 + wid;             // layer-2 output (0..4095)
    const float4* __restrict__ w1r = (const float4*)&g_W1t[(size_t)j1 << 12];
    const float4* __restrict__ w2r = (const float4*)&g_W2t[(size_t)j2 << 10];
    const float b1j = b1[j1];
    const float b2j = b2[j2];

    // per-warp RK4 state for output j2 (lane 0 authoritative)
    float wcur = g_w[j2];
    float k1 = 0.f, k2 = 0.f, k3 = 0.f;

    for (int stage = 0; stage < 4 * (T_STEPS - 1); ++stage) {
        const int st4 = stage & 3;
        // ---- load current stage input vector into smem ----
        const float* __restrict__ win = (st4 == 0) ? g_w : g_ws;
        {
            const float4* w4 = (const float4*)win;
            float4* s4 = (float4*)sw;
            s4[tid] = w4[tid];                        // 1024 threads x 16B = 16KB
        }
        __syncthreads();

        // ---- layer 1: t[j1] = tanh(win . W1t[j1] + b1) ----
        {
            const float4* sw4 = (const float4*)sw;
            float s = 0.f;
#pragma unroll
            for (int k4 = tin; k4 < 1024; k4 += 128) {
                float4 a = w1r[k4];
                float4 b = sw4[k4];
                s += a.x * b.x + a.y * b.y + a.z * b.z + a.w * b.w;
            }
#pragma unroll
            for (int o = 16; o; o >>= 1) s += __shfl_xor_sync(0xffffffffu, s, o);
            if ((tin & 31) == 0) redA[grp][wgrp] = s;
        }
        __syncthreads();
        if (tid < 8) {
            float tot = redA[tid][0] + redA[tid][1] + redA[tid][2] + redA[tid][3];
            g_t[blockIdx.x * 8 + tid] = tanhf(tot + b1j - b1j + b1[blockIdx.x * 8 + tid]);
        }
        gridsync();

        // ---- layer 2: z[j2] = t . W2t[j2] + b2 ; fused RK4 stage update ----
        st[tid & (BN - 1)] = g_t[tid & (BN - 1)];     // first 1024 threads cover all
        __syncthreads();
        {
            const float4* st4p = (const float4*)st;
            float s = 0.f;
#pragma unroll
            for (int k4 = lane; k4 < 256; k4 += 32) {
                float4 a = w2r[k4];
                float4 b = st4p[k4];
                s += a.x * b.x + a.y * b.y + a.z * b.z + a.w * b.w;
            }
#pragma unroll
            for (int o = 16; o; o >>= 1) s += __shfl_xor_sync(0xffffffffu, s, o);
            if (lane == 0) {
                float z = s + b2j;
                if (st4 == 0) {
                    k1 = z;
                    g_ws[j2] = wcur + (h * (1.f / 3.f)) * z;
                } else if (st4 == 1) {
                    k2 = z;
                    g_ws[j2] = wcur + h * (z - k1 * (1.f / 3.f));
                } else if (st4 == 2) {
                    k3 = z;
                    g_ws[j2] = wcur + h * (k1 - k2 + z);
                } else {
                    wcur += h * 0.125f * (k1 + 3.f * (k2 + k3) + z);
                    g_w[j2] = wcur;
                }
            }
        }
        gridsync();
    }
}

// ---------------- xw: z[n] = dis[n] * (x_last[n] @ W_T); acc[n] = dis[n]*z[n] ----------------
__global__ void xw_kernel(const float* __restrict__ xlast, int n) {
    __shared__ float Ws[64 * 64];
    __shared__ float xs[64 * 64];
    int n0 = blockIdx.x * 64;
    for (int i = threadIdx.x; i < 4096; i += 256) Ws[i] = g_w[i];
    for (int i = threadIdx.x; i < 4096; i += 256) {
        int r = i >> 6, c = i & 63, nn = n0 + r;
        xs[i] = (nn < n) ? xlast[(size_t)nn * 64 + c] : 0.f;
    }
    __syncthreads();
    int tx = threadIdx.x & 15, ty = threadIdx.x >> 4;
    float acc[4][4] = {};
#pragma unroll 4
    for (int k = 0; k < 64; ++k) {
        float4 b = *(const float4*)&Ws[k * 64 + tx * 4];
#pragma unroll
        for (int i = 0; i < 4; ++i) {
            float a = xs[(ty * 4 + i) * 64 + k];
            acc[i][0] += a * b.x; acc[i][1] += a * b.y;
            acc[i][2] += a * b.z; acc[i][3] += a * b.w;
        }
    }
    float* gz = (float*)g_z4;
    float* ga = (float*)g_acc4;
#pragma unroll
    for (int i = 0; i < 4; ++i) {
        int nn = n0 + ty * 4 + i;
        if (nn < n) {
            float dn = g_dis[nn];
            float4 z, a2;
            z.x = dn * acc[i][0]; z.y = dn * acc[i][1];
            z.z = dn * acc[i][2]; z.w = dn * acc[i][3];
            a2.x = dn * z.x; a2.y = dn * z.y; a2.z = dn * z.z; a2.w = dn * z.w;
            *(float4*)&gz[nn * 64 + tx * 4] = z;   // edge gather table
            *(float4*)&ga[nn * 64 + tx * 4] = a2;  // self-loop term = accumulator init
        }
    }
}

// ---------------- scatter: acc[col] += dis[col] * z[row], vec4 reductions ----------------
__global__ void scatter_kernel(const int* __restrict__ ei, int e) {
    int idx = blockIdx.x * 256 + threadIdx.x;
    if (idx >= e * 16) return;
    int eg = idx >> 4, q = idx & 15;
    int r = __ldg(&ei[eg]);
    int c = __ldg(&ei[e + eg]);
    float dc = g_dis[c];
    float4 v = g_z4[r * 16 + q];
    v.x *= dc; v.y *= dc; v.z *= dc; v.w *= dc;
    float4* p = &g_acc4[c * 16 + q];
    asm volatile("red.global.add.v4.f32 [%0], {%1, %2, %3, %4};"
                 :: "l"(p), "f"(v.x), "f"(v.y), "f"(v.z), "f"(v.w) : "memory");
}

// ---------------- hA/hB: h = relu(acc); hA = h@W[0:64]+b1; hB = h@W[64:128] ----------------
__global__ void hab_kernel(const float* __restrict__ mw1, const float* __restrict__ mb1,
                           int n) {
    int sel = blockIdx.y;  // 0 -> A (+bias), 1 -> B
    __shared__ float Ws[64 * 64];
    __shared__ float xs[64 * 64];
    const float* ga = (const float*)g_acc4;
    int n0 = blockIdx.x * 64;
    for (int i = threadIdx.x; i < 4096; i += 256) Ws[i] = mw1[sel * 4096 + i];
    for (int i = threadIdx.x; i < 4096; i += 256) {
        int r = i >> 6, c = i & 63, nn = n0 + r;
        xs[i] = (nn < n) ? fmaxf(ga[nn * 64 + c], 0.f) : 0.f;
    }
    __syncthreads();
    int tx = threadIdx.x & 15, ty = threadIdx.x >> 4;
    float acc[4][4] = {};
#pragma unroll 4
    for (int k = 0; k < 64; ++k) {
        float4 b = *(const float4*)&Ws[k * 64 + tx * 4];
#pragma unroll
        for (int i = 0; i < 4; ++i) {
            float a = xs[(ty * 4 + i) * 64 + k];
            acc[i][0] += a * b.x; acc[i][1] += a * b.y;
            acc[i][2] += a * b.z; acc[i][3] += a * b.w;
        }
    }
    float4 bb = make_float4(0.f, 0.f, 0.f, 0.f);
    if (sel == 0) {
        bb.x = mb1[tx * 4 + 0]; bb.y = mb1[tx * 4 + 1];
        bb.z = mb1[tx * 4 + 2]; bb.w = mb1[tx * 4 + 3];
    }
    float* out = sel ? (float*)g_hB4 : (float*)g_hA4;
#pragma unroll
    for (int i = 0; i < 4; ++i) {
        int nn = n0 + ty * 4 + i;
        if (nn < n) {
            float4 v;
            v.x = acc[i][0] + bb.x; v.y = acc[i][1] + bb.y;
            v.z = acc[i][2] + bb.z; v.w = acc[i][3] + bb.w;
            *(float4*)&out[nn * 64 + tx * 4] = v;
        }
    }
}

// ---------------- edge MLP: out[e] = relu(hA[r]+hB[c]+ea@C) . w2 + b2 ----------------
__global__ void edge_kernel(const float* __restrict__ ea, const int* __restrict__ ei,
                            const float* __restrict__ mw1, const float* __restrict__ w2,
                            const float* __restrict__ b2, float* __restrict__ out, int e) {
    __shared__ float Cs[16 * 64];
    __shared__ float w2s[64];
    for (int i = threadIdx.x; i < 1024; i += 256) Cs[i] = mw1[128 * 64 + i];
    if (threadIdx.x < 64) w2s[threadIdx.x] = w2[threadIdx.x];
    __syncthreads();
    int warp = threadIdx.x >> 5, lane = threadIdx.x & 31;
    int eg = blockIdx.x * 8 + warp;
    if (eg >= e) return;
    const float* hA = (const float*)g_hA4;
    const float* hB = (const float*)g_hB4;
    int r = __ldg(&ei[eg]);
    int c = __ldg(&ei[e + eg]);
    float av = (lane < 16) ? __ldg(&ea[(size_t)eg * 16 + lane]) : 0.f;
    int j0 = lane, j1 = lane + 32;
    float s0 = hA[r * 64 + j0] + hB[c * 64 + j0];
    float s1 = hA[r * 64 + j1] + hB[c * 64 + j1];
#pragma unroll
    for (int f = 0; f < 16; ++f) {
        float a = __shfl_sync(0xffffffffu, av, f);
        s0 += a * Cs[f * 64 + j0];
        s1 += a * Cs[f * 64 + j1];
    }
    float p = fmaxf(s0, 0.f) * w2s[j0] + fmaxf(s1, 0.f) * w2s[j1];
#pragma unroll
    for (int o = 16; o; o >>= 1) p += __shfl_xor_sync(0xffffffffu, p, o);
    if (lane == 0) out[eg] = p + b2[0];
}

// ---------------- launcher ----------------
extern "C" void kernel_launch(void* const* d_in, const int* in_sizes, int n_in,
                              void* d_out, int out_size) {
    const float* x_seq = (const float*)d_in[0];
    const float* ea    = (const float*)d_in[1];
    const float* iw    = (const float*)d_in[2];
    const float* W1    = (const float*)d_in[3];
    const float* b1o   = (const float*)d_in[4];
    const float* W2    = (const float*)d_in[5];
    const float* b2o   = (const float*)d_in[6];
    const float* mw1   = (const float*)d_in[7];
    const float* mb1   = (const float*)d_in[8];
    const float* mw2   = (const float*)d_in[9];
    const float* mb2   = (const float*)d_in[10];
    const int*   ei    = (const int*)d_in[11];
    float* out = (float*)d_out;

    const int n = NN;
    const int e = EE;
    const float* xlast = x_seq + (size_t)(T_STEPS - 1) * n * 64;
    const float h = 1.0f / (float)(T_STEPS - 1);

    // degree / normalization (independent of ODE)
    init_kernel<<<(n + 255) / 256, 256>>>(iw, n);
    deg_kernel<<<(e + 255) / 256, 256>>>(ei, e);
    rsqrt_kernel<<<(n + 255) / 256, 256>>>(n);

    // one-time weight transposes for contiguous GEMV rows
    {
        float* w1t; cudaGetSymbolAddress((void**)&w1t, g_W1t);
        float* w2t; cudaGetSymbolAddress((void**)&w2t, g_W2t);
        dim3 t1g(BN / 32, FLAT / 32);    // src [4096][1024]
        transpose_kernel<<<t1g, dim3(32, 8)>>>(W1, w1t, FLAT, BN);
        dim3 t2g(FLAT / 32, BN / 32);    // src [1024][4096]
        transpose_kernel<<<t2g, dim3(32, 8)>>>(W2, w2t, BN, FLAT);
    }

    // full weight ODE in one persistent kernel
    ode_persist<<<NB_ODE, 1024>>>(b1o, b2o, h);

    // GCN
    xw_kernel<<<(n + 63) / 64, 256>>>(xlast, n);
    scatter_kernel<<<(e * 16 + 255) / 256, 256>>>(ei, e);

    // node-side halves of the edge MLP first layer
    dim3 hg((n + 63) / 64, 2);
    hab_kernel<<<hg, 256>>>(mw1, mb1, n);

    // per-edge MLP
    edge_kernel<<<(e + 7) / 8, 256>>>(ea, ei, mw1, mw2, mb2, out, e);
}

// round 3
// speedup vs baseline: 1.2305x; 1.1073x over previous
#include <cuda_runtime.h>

// Problem constants (fixed by the dataset)
#define T_STEPS 8
#define NN      100000
#define EE      1600000
#define FLAT    4096    // 64*64
#define BN      1024    // bottleneck
#define NB_ODE  128     // persistent ODE grid (1 block/SM, co-resident)

// ---------------- device scratch (no allocs allowed) ----------------
__device__ float  g_w[FLAT];
__device__ float  g_ws[FLAT];
__device__ float  g_t[BN];
__device__ float  g_W1t[BN * FLAT];   // transposed: row j (1024 rows) x k (4096)
__device__ float  g_W2t[FLAT * BN];   // transposed: row j (4096 rows) x k (1024)
__device__ unsigned g_barcnt;
__device__ unsigned g_bargen;
__device__ float  g_dis[NN];
__device__ float4 g_z4[NN * 16];    // dis[n] * (x W_T)   [N,64]
__device__ float4 g_acc4[NN * 16];  // scatter accumulator [N,64]
__device__ float4 g_hA4[NN * 16];   // h @ A + b1          [N,64]
__device__ float4 g_hB4[NN * 16];   // h @ B               [N,64]

// ---------------- init: copy w0, deg := 1 (self loop) ----------------
__global__ void init_kernel(const float* __restrict__ iw, int n) {
    int i = blockIdx.x * 256 + threadIdx.x;
    if (i < FLAT) g_w[i] = iw[i];
    if (i < n)    g_dis[i] = 1.0f;
}

// ---------------- degree scatter ----------------
__global__ void deg_kernel(const int* __restrict__ ei, int e) {
    int i = blockIdx.x * 256 + threadIdx.x;
    if (i < e) atomicAdd(&g_dis[ei[e + i]], 1.0f);
}

__global__ void rsqrt_kernel(int n) {
    int i = blockIdx.x * 256 + threadIdx.x;
    if (i < n) g_dis[i] = rsqrtf(g_dis[i]);
}

// ---------------- 32x32 tiled transpose: dst[C][R] = src[R][C]^T ----------------
__global__ void transpose_kernel(const float* __restrict__ src, float* __restrict__ dst,
                                 int R, int C) {
    __shared__ float tile[32][33];
    int bx = blockIdx.x * 32, by = blockIdx.y * 32;
    int x = bx + threadIdx.x;
#pragma unroll
    for (int i = 0; i < 32; i += 8) {
        int y = by + threadIdx.y + i;
        tile[threadIdx.y + i][threadIdx.x] = src[(size_t)y * C + x];
    }
    __syncthreads();
    int x2 = by + threadIdx.x;
#pragma unroll
    for (int i = 0; i < 32; i += 8) {
        int y2 = bx + threadIdx.y + i;
        dst[(size_t)y2 * R + x2] = tile[threadIdx.x][threadIdx.y + i];
    }
}

// ---------------- grid barrier for the persistent ODE ----------------
__device__ __forceinline__ void gridsync() {
    __syncthreads();
    if (threadIdx.x == 0) {
        __threadfence();
        unsigned gen = *(volatile unsigned*)&g_bargen;
        if (atomicAdd(&g_barcnt, 1u) == NB_ODE - 1) {
            g_barcnt = 0;
            __threadfence();
            *(volatile unsigned*)&g_bargen = gen + 1;
        } else {
            while (*(volatile unsigned*)&g_bargen == gen) __nanosleep(32);
        }
        __threadfence();
    }
    __syncthreads();
}

// ---------------- persistent ODE ----------------
// W1 slice resident in SMEM (128KB/block), W2 slice resident in registers
// (1 row per warp = 8 float4/thread). Per-stage global traffic: ~20KB/SM.
// smem layout (floats): sW1[32768] | sw[4096] | st[1024] | red[32]
#define ODE_SMEM_FLOATS (32768 + 4096 + 1024 + 32)

__global__ __launch_bounds__(1024, 1)
void ode_persist(const float* __restrict__ b1, const float* __restrict__ b2, float h) {
    extern __shared__ float sm[];
    float* sW1 = sm;
    float* sw  = sm + 32768;
    float* st  = sm + 32768 + 4096;
    float* red = sm + 32768 + 4096 + 1024;   // [8 groups][4 warps]

    const int tid  = threadIdx.x;
    const int b    = blockIdx.x;
    const int lane = tid & 31;
    const int wid  = tid >> 5;        // 0..31 -> layer-2 output row
    const int grp  = tid >> 7;        // 0..7  -> layer-1 output row
    const int tin  = tid & 127;
    const int wgrp = tin >> 5;        // warp within group

    // ---- one-time: W1 slice (rows 8b..8b+8) into smem ----
    {
        const float4* src = (const float4*)(g_W1t + ((size_t)b * 8) * 4096);
        float4* dst = (float4*)sW1;
#pragma unroll
        for (int i = 0; i < 8; ++i) dst[tid + 1024 * i] = src[tid + 1024 * i];
    }
    // ---- one-time: W2 row (32b + wid) into registers ----
    float4 w2r[8];
    {
        const float4* src = (const float4*)(g_W2t + ((size_t)(b * 32 + wid)) * 1024);
#pragma unroll
        for (int i = 0; i < 8; ++i) w2r[i] = src[lane + 32 * i];
    }
    const int   j2  = b * 32 + wid;
    const float b2j = b2[j2];
    float wcur = g_w[j2];            // fresh from init_kernel (L1 flushed per launch)
    float k1 = 0.f, k2 = 0.f, k3 = 0.f;
    __syncthreads();

    for (int stage = 0; stage < 4 * (T_STEPS - 1); ++stage) {
        const int st4 = stage & 3;
        // ---- stage input vector -> smem (L2-coherent read) ----
        {
            const float4* win = (const float4*)(st4 == 0 ? g_w : g_ws);
            ((float4*)sw)[tid] = __ldcg(win + tid);
        }
        __syncthreads();

        // ---- layer 1: t[j1] = tanh(sw . W1row + b1) ----
        {
            const float4* wrow = (const float4*)(sW1 + (size_t)grp * 4096);
            const float4* sw4  = (const float4*)sw;
            float s = 0.f;
#pragma unroll
            for (int i = 0; i < 8; ++i) {
                float4 a = wrow[tin + 128 * i];
                float4 v = sw4[tin + 128 * i];
                s += a.x * v.x + a.y * v.y + a.z * v.z + a.w * v.w;
            }
#pragma unroll
            for (int o = 16; o; o >>= 1) s += __shfl_xor_sync(0xffffffffu, s, o);
            if (lane == 0) red[grp * 4 + wgrp] = s;
        }
        __syncthreads();
        if (tid < 8) {
            float tot = red[tid * 4] + red[tid * 4 + 1] + red[tid * 4 + 2] + red[tid * 4 + 3];
            g_t[b * 8 + tid] = tanhf(tot + b1[b * 8 + tid]);
        }
        gridsync();

        // ---- layer 2: z[j2] = t . W2row + b2 ; fused RK4 stage update ----
        if (tid < 256) ((float4*)st)[tid] = __ldcg(((const float4*)g_t) + tid);
        __syncthreads();
        {
            const float4* st4p = (const float4*)st;
            float s = 0.f;
#pragma unroll
            for (int i = 0; i < 8; ++i) {
                float4 a = w2r[i];
                float4 v = st4p[lane + 32 * i];
                s += a.x * v.x + a.y * v.y + a.z * v.z + a.w * v.w;
            }
#pragma unroll
            for (int o = 16; o; o >>= 1) s += __shfl_xor_sync(0xffffffffu, s, o);
            if (lane == 0) {
                float z = s + b2j;
                if (st4 == 0) {
                    k1 = z;
                    g_ws[j2] = wcur + (h * (1.f / 3.f)) * z;
                } else if (st4 == 1) {
                    k2 = z;
                    g_ws[j2] = wcur + h * (z - k1 * (1.f / 3.f));
                } else if (st4 == 2) {
                    k3 = z;
                    g_ws[j2] = wcur + h * (k1 - k2 + z);
                } else {
                    wcur += h * 0.125f * (k1 + 3.f * (k2 + k3) + z);
                    g_w[j2] = wcur;
                }
            }
        }
        if (stage != 4 * (T_STEPS - 1) - 1) gridsync();
    }
}

// ---------------- xw: z[n] = dis[n] * (x_last[n] @ W_T); acc[n] = dis[n]*z[n] ----------------
__global__ void xw_kernel(const float* __restrict__ xlast, int n) {
    __shared__ float Ws[64 * 64];
    __shared__ float xs[64 * 64];
    int n0 = blockIdx.x * 64;
    for (int i = threadIdx.x; i < 4096; i += 256) Ws[i] = g_w[i];
    for (int i = threadIdx.x; i < 4096; i += 256) {
        int r = i >> 6, c = i & 63, nn = n0 + r;
        xs[i] = (nn < n) ? xlast[(size_t)nn * 64 + c] : 0.f;
    }
    __syncthreads();
    int tx = threadIdx.x & 15, ty = threadIdx.x >> 4;
    float acc[4][4] = {};
#pragma unroll 4
    for (int k = 0; k < 64; ++k) {
        float4 b = *(const float4*)&Ws[k * 64 + tx * 4];
#pragma unroll
        for (int i = 0; i < 4; ++i) {
            float a = xs[(ty * 4 + i) * 64 + k];
            acc[i][0] += a * b.x; acc[i][1] += a * b.y;
            acc[i][2] += a * b.z; acc[i][3] += a * b.w;
        }
    }
    float* gz = (float*)g_z4;
    float* ga = (float*)g_acc4;
#pragma unroll
    for (int i = 0; i < 4; ++i) {
        int nn = n0 + ty * 4 + i;
        if (nn < n) {
            float dn = g_dis[nn];
            float4 z, a2;
            z.x = dn * acc[i][0]; z.y = dn * acc[i][1];
            z.z = dn * acc[i][2]; z.w = dn * acc[i][3];
            a2.x = dn * z.x; a2.y = dn * z.y; a2.z = dn * z.z; a2.w = dn * z.w;
            *(float4*)&gz[nn * 64 + tx * 4] = z;   // edge gather table
            *(float4*)&ga[nn * 64 + tx * 4] = a2;  // self-loop term = accumulator init
        }
    }
}

// ---------------- scatter: acc[col] += dis[col] * z[row], vec4 reductions ----------------
__global__ void scatter_kernel(const int* __restrict__ ei, int e) {
    int idx = blockIdx.x * 256 + threadIdx.x;
    if (idx >= e * 16) return;
    int eg = idx >> 4, q = idx & 15;
    int r = __ldg(&ei[eg]);
    int c = __ldg(&ei[e + eg]);
    float dc = g_dis[c];
    float4 v = g_z4[r * 16 + q];
    v.x *= dc; v.y *= dc; v.z *= dc; v.w *= dc;
    float4* p = &g_acc4[c * 16 + q];
    asm volatile("red.global.add.v4.f32 [%0], {%1, %2, %3, %4};"
                 :: "l"(p), "f"(v.x), "f"(v.y), "f"(v.z), "f"(v.w) : "memory");
}

// ---------------- hA/hB fused: h = relu(acc); hA = h@W[0:64]+b1; hB = h@W[64:128] ----------------
__global__ void hab_kernel(const float* __restrict__ mw1, const float* __restrict__ mb1,
                           int n) {
    __shared__ float Ws[64 * 64];
    __shared__ float xs[64 * 64];
    const float* ga = (const float*)g_acc4;
    int n0 = blockIdx.x * 64;
    for (int i = threadIdx.x; i < 4096; i += 256) {
        int r = i >> 6, c = i & 63, nn = n0 + r;
        xs[i] = (nn < n) ? fmaxf(ga[nn * 64 + c], 0.f) : 0.f;
    }
    int tx = threadIdx.x & 15, ty = threadIdx.x >> 4;
#pragma unroll
    for (int sel = 0; sel < 2; ++sel) {
        __syncthreads();
        for (int i = threadIdx.x; i < 4096; i += 256) Ws[i] = mw1[sel * 4096 + i];
        __syncthreads();
        float acc[4][4] = {};
#pragma unroll 4
        for (int k = 0; k < 64; ++k) {
            float4 b = *(const float4*)&Ws[k * 64 + tx * 4];
#pragma unroll
            for (int i = 0; i < 4; ++i) {
                float a = xs[(ty * 4 + i) * 64 + k];
                acc[i][0] += a * b.x; acc[i][1] += a * b.y;
                acc[i][2] += a * b.z; acc[i][3] += a * b.w;
            }
        }
        float4 bb = make_float4(0.f, 0.f, 0.f, 0.f);
        if (sel == 0) {
            bb.x = mb1[tx * 4 + 0]; bb.y = mb1[tx * 4 + 1];
            bb.z = mb1[tx * 4 + 2]; bb.w = mb1[tx * 4 + 3];
        }
        float* out = sel ? (float*)g_hB4 : (float*)g_hA4;
#pragma unroll
        for (int i = 0; i < 4; ++i) {
            int nn = n0 + ty * 4 + i;
            if (nn < n) {
                float4 v;
                v.x = acc[i][0] + bb.x; v.y = acc[i][1] + bb.y;
                v.z = acc[i][2] + bb.z; v.w = acc[i][3] + bb.w;
                *(float4*)&out[nn * 64 + tx * 4] = v;
            }
        }
    }
}

// ---------------- edge MLP: out[e] = relu(hA[r]+hB[c]+ea@C) . w2 + b2 ----------------
__global__ void edge_kernel(const float* __restrict__ ea, const int* __restrict__ ei,
                            const float* __restrict__ mw1, const float* __restrict__ w2,
                            const float* __restrict__ b2, float* __restrict__ out, int e) {
    __shared__ float Cs[16 * 64];
    __shared__ float w2s[64];
    for (int i = threadIdx.x; i < 1024; i += 256) Cs[i] = mw1[128 * 64 + i];
    if (threadIdx.x < 64) w2s[threadIdx.x] = w2[threadIdx.x];
    __syncthreads();
    int warp = threadIdx.x >> 5, lane = threadIdx.x & 31;
    int eg = blockIdx.x * 8 + warp;
    if (eg >= e) return;
    const float* hA = (const float*)g_hA4;
    const float* hB = (const float*)g_hB4;
    int r = __ldg(&ei[eg]);
    int c = __ldg(&ei[e + eg]);
    float av = (lane < 16) ? __ldg(&ea[(size_t)eg * 16 + lane]) : 0.f;
    int j0 = lane, j1 = lane + 32;
    float s0 = hA[r * 64 + j0] + hB[c * 64 + j0];
    float s1 = hA[r * 64 + j1] + hB[c * 64 + j1];
#pragma unroll
    for (int f = 0; f < 16; ++f) {
        float a = __shfl_sync(0xffffffffu, av, f);
        s0 += a * Cs[f * 64 + j0];
        s1 += a * Cs[f * 64 + j1];
    }
    float p = fmaxf(s0, 0.f) * w2s[j0] + fmaxf(s1, 0.f) * w2s[j1];
#pragma unroll
    for (int o = 16; o; o >>= 1) p += __shfl_xor_sync(0xffffffffu, p, o);
    if (lane == 0) out[eg] = p + b2[0];
}

// ---------------- launcher ----------------
extern "C" void kernel_launch(void* const* d_in, const int* in_sizes, int n_in,
                              void* d_out, int out_size) {
    const float* x_seq = (const float*)d_in[0];
    const float* ea    = (const float*)d_in[1];
    const float* iw    = (const float*)d_in[2];
    const float* W1    = (const float*)d_in[3];
    const float* b1o   = (const float*)d_in[4];
    const float* W2    = (const float*)d_in[5];
    const float* b2o   = (const float*)d_in[6];
    const float* mw1   = (const float*)d_in[7];
    const float* mb1   = (const float*)d_in[8];
    const float* mw2   = (const float*)d_in[9];
    const float* mb2   = (const float*)d_in[10];
    const int*   ei    = (const int*)d_in[11];
    float* out = (float*)d_out;

    const int n = NN;
    const int e = EE;
    const float* xlast = x_seq + (size_t)(T_STEPS - 1) * n * 64;
    const float h = 1.0f / (float)(T_STEPS - 1);

    // opt-in to large dynamic smem for the persistent ODE (idempotent)
    cudaFuncSetAttribute(ode_persist, cudaFuncAttributeMaxDynamicSharedMemorySize,
                         ODE_SMEM_FLOATS * 4);

    // degree / normalization (independent of ODE)
    init_kernel<<<(n + 255) / 256, 256>>>(iw, n);
    deg_kernel<<<(e + 255) / 256, 256>>>(ei, e);
    rsqrt_kernel<<<(n + 255) / 256, 256>>>(n);

    // one-time weight transposes for contiguous GEMV rows
    {
        float* w1t; cudaGetSymbolAddress((void**)&w1t, g_W1t);
        float* w2t; cudaGetSymbolAddress((void**)&w2t, g_W2t);
        dim3 t1g(BN / 32, FLAT / 32);    // src [4096][1024]
        transpose_kernel<<<t1g, dim3(32, 8)>>>(W1, w1t, FLAT, BN);
        dim3 t2g(FLAT / 32, BN / 32);    // src [1024][4096]
        transpose_kernel<<<t2g, dim3(32, 8)>>>(W2, w2t, BN, FLAT);
    }

    // full weight ODE in one persistent kernel (weights SMEM/register resident)
    ode_persist<<<NB_ODE, 1024, ODE_SMEM_FLOATS * 4>>>(b1o, b2o, h);

    // GCN
    xw_kernel<<<(n + 63) / 64, 256>>>(xlast, n);
    scatter_kernel<<<(e * 16 + 255) / 256, 256>>>(ei, e);

    // node-side halves of the edge MLP first layer (fused A+B, single acc read)
    hab_kernel<<<(n + 63) / 64, 256>>>(mw1, mb1, n);

    // per-edge MLP
    edge_kernel<<<(e + 7) / 8, 256>>>(ea, ei, mw1, mw2, mb2, out, e);
}

// round 4
// speedup vs baseline: 1.2639x; 1.0271x over previous
#include <cuda_runtime.h>

// Problem constants (fixed by the dataset)
#define T_STEPS 8
#define NN      100000
#define EE      1600000
#define FLAT    4096    // 64*64
#define BN      1024    // bottleneck
#define NB_ODE  128     // persistent ODE grid (1 block/SM, co-resident)
#define NB_SCAN 98      // ceil(NN/1024)

// ---------------- device scratch (no allocs allowed) ----------------
__device__ float  g_w[FLAT];
__device__ float  g_ws[FLAT];
__device__ float  g_t[BN];
__device__ float  g_W1t[BN * FLAT];   // transposed: row j (1024 rows) x k (4096)
__device__ float  g_W2t[FLAT * BN];   // transposed: row j (4096 rows) x k (1024)
__device__ unsigned g_barcnt;
__device__ unsigned g_bargen;
__device__ float  g_dis[NN];
__device__ int    g_cnt[NN];        // in-degree (no self)
__device__ int    g_base[NN + 1];   // CSR row offsets (by destination)
__device__ int    g_cur[NN];        // placement cursors
__device__ int    g_src[EE];        // CSR: source node per in-edge
__device__ int    g_bsum[NB_SCAN];
__device__ int    g_boff[NB_SCAN];
__device__ float4 g_z4[NN * 16];    // dis[n] * (x W_T)   [N,64]
__device__ float4 g_acc4[NN * 16];  // aggregated messages [N,64]
__device__ float4 g_hA4[NN * 16];   // h @ A + b1          [N,64]
__device__ float4 g_hB4[NN * 16];   // h @ B               [N,64]

// ---------------- init: copy w0, zero in-degree counters ----------------
__global__ void init_kernel(const float* __restrict__ iw, int n) {
    int i = blockIdx.x * 256 + threadIdx.x;
    if (i < FLAT) g_w[i] = iw[i];
    if (i < n)    g_cnt[i] = 0;
}

// ---------------- in-degree count ----------------
__global__ void count_kernel(const int* __restrict__ ei, int e) {
    int i = blockIdx.x * 256 + threadIdx.x;
    if (i < e) atomicAdd(&g_cnt[ei[e + i]], 1);
}

// ---------------- dis = rsqrt(deg), deg = cnt + 1 (self loop) ----------------
__global__ void dis_kernel(int n) {
    int i = blockIdx.x * 256 + threadIdx.x;
    if (i < n) g_dis[i] = rsqrtf(1.0f + (float)g_cnt[i]);
}

// ---------------- CSR offset scan (3 small kernels) ----------------
__global__ void scan1_kernel(int n) {            // block sums
    __shared__ int sm_[1024];
    int i = blockIdx.x * 1024 + threadIdx.x;
    sm_[threadIdx.x] = (i < n) ? g_cnt[i] : 0;
    __syncthreads();
#pragma unroll
    for (int o = 512; o; o >>= 1) {
        if (threadIdx.x < o) sm_[threadIdx.x] += sm_[threadIdx.x + o];
        __syncthreads();
    }
    if (threadIdx.x == 0) g_bsum[blockIdx.x] = sm_[0];
}

__global__ void scan2_kernel(int nb) {           // serial scan of block sums
    __shared__ int sb[NB_SCAN];
    if (threadIdx.x < nb) sb[threadIdx.x] = g_bsum[threadIdx.x];
    __syncthreads();
    if (threadIdx.x == 0) {
        int run = 0;
        for (int b = 0; b < nb; ++b) { g_boff[b] = run; run += sb[b]; }
        g_base[NN] = run;            // == EE
    }
}

__global__ void scan3_kernel(int n) {            // in-block exclusive scan + offset
    __shared__ int sm_[1024];
    int i = blockIdx.x * 1024 + threadIdx.x;
    int v = (i < n) ? g_cnt[i] : 0;
    sm_[threadIdx.x] = v;
    __syncthreads();
#pragma unroll
    for (int o = 1; o < 1024; o <<= 1) {         // Hillis-Steele inclusive
        int t = (threadIdx.x >= o) ? sm_[threadIdx.x - o] : 0;
        __syncthreads();
        sm_[threadIdx.x] += t;
        __syncthreads();
    }
    if (i < n) {
        int excl = sm_[threadIdx.x] - v + g_boff[blockIdx.x];
        g_base[i] = excl;
        g_cur[i]  = excl;
    }
}

// ---------------- CSR placement ----------------
__global__ void place_kernel(const int* __restrict__ ei, int e) {
    int i = blockIdx.x * 256 + threadIdx.x;
    if (i < e) {
        int c = ei[e + i];
        int p = atomicAdd(&g_cur[c], 1);
        g_src[p] = ei[i];
    }
}

// ---------------- 32x32 tiled transpose: dst[C][R] = src[R][C]^T ----------------
__global__ void transpose_kernel(const float* __restrict__ src, float* __restrict__ dst,
                                 int R, int C) {
    __shared__ float tile[32][33];
    int bx = blockIdx.x * 32, by = blockIdx.y * 32;
    int x = bx + threadIdx.x;
#pragma unroll
    for (int i = 0; i < 32; i += 8) {
        int y = by + threadIdx.y + i;
        tile[threadIdx.y + i][threadIdx.x] = src[(size_t)y * C + x];
    }
    __syncthreads();
    int x2 = by + threadIdx.x;
#pragma unroll
    for (int i = 0; i < 32; i += 8) {
        int y2 = bx + threadIdx.y + i;
        dst[(size_t)y2 * R + x2] = tile[threadIdx.x][threadIdx.y + i];
    }
}

// ---------------- grid barrier for the persistent ODE ----------------
__device__ __forceinline__ void gridsync() {
    __syncthreads();
    if (threadIdx.x == 0) {
        __threadfence();
        unsigned gen = *(volatile unsigned*)&g_bargen;
        if (atomicAdd(&g_barcnt, 1u) == NB_ODE - 1) {
            g_barcnt = 0;
            __threadfence();
            *(volatile unsigned*)&g_bargen = gen + 1;
        } else {
            while (*(volatile unsigned*)&g_bargen == gen) __nanosleep(32);
        }
        __threadfence();
    }
    __syncthreads();
}

// ---------------- persistent ODE (unchanged from R3) ----------------
#define ODE_SMEM_FLOATS (32768 + 4096 + 1024 + 32)

__global__ __launch_bounds__(1024, 1)
void ode_persist(const float* __restrict__ b1, const float* __restrict__ b2, float h) {
    extern __shared__ float sm[];
    float* sW1 = sm;
    float* sw  = sm + 32768;
    float* st  = sm + 32768 + 4096;
    float* red = sm + 32768 + 4096 + 1024;   // [8 groups][4 warps]

    const int tid  = threadIdx.x;
    const int b    = blockIdx.x;
    const int lane = tid & 31;
    const int wid  = tid >> 5;
    const int grp  = tid >> 7;
    const int tin  = tid & 127;
    const int wgrp = tin >> 5;

    {
        const float4* src = (const float4*)(g_W1t + ((size_t)b * 8) * 4096);
        float4* dst = (float4*)sW1;
#pragma unroll
        for (int i = 0; i < 8; ++i) dst[tid + 1024 * i] = src[tid + 1024 * i];
    }
    float4 w2r[8];
    {
        const float4* src = (const float4*)(g_W2t + ((size_t)(b * 32 + wid)) * 1024);
#pragma unroll
        for (int i = 0; i < 8; ++i) w2r[i] = src[lane + 32 * i];
    }
    const int   j2  = b * 32 + wid;
    const float b2j = b2[j2];
    float wcur = g_w[j2];
    float k1 = 0.f, k2 = 0.f, k3 = 0.f;
    __syncthreads();

    for (int stage = 0; stage < 4 * (T_STEPS - 1); ++stage) {
        const int st4 = stage & 3;
        {
            const float4* win = (const float4*)(st4 == 0 ? g_w : g_ws);
            ((float4*)sw)[tid] = __ldcg(win + tid);
        }
        __syncthreads();

        {
            const float4* wrow = (const float4*)(sW1 + (size_t)grp * 4096);
            const float4* sw4  = (const float4*)sw;
            float s = 0.f;
#pragma unroll
            for (int i = 0; i < 8; ++i) {
                float4 a = wrow[tin + 128 * i];
                float4 v = sw4[tin + 128 * i];
                s += a.x * v.x + a.y * v.y + a.z * v.z + a.w * v.w;
            }
#pragma unroll
            for (int o = 16; o; o >>= 1) s += __shfl_xor_sync(0xffffffffu, s, o);
            if (lane == 0) red[grp * 4 + wgrp] = s;
        }
        __syncthreads();
        if (tid < 8) {
            float tot = red[tid * 4] + red[tid * 4 + 1] + red[tid * 4 + 2] + red[tid * 4 + 3];
            g_t[b * 8 + tid] = tanhf(tot + b1[b * 8 + tid]);
        }
        gridsync();

        if (tid < 256) ((float4*)st)[tid] = __ldcg(((const float4*)g_t) + tid);
        __syncthreads();
        {
            const float4* st4p = (const float4*)st;
            float s = 0.f;
#pragma unroll
            for (int i = 0; i < 8; ++i) {
                float4 a = w2r[i];
                float4 v = st4p[lane + 32 * i];
                s += a.x * v.x + a.y * v.y + a.z * v.z + a.w * v.w;
            }
#pragma unroll
            for (int o = 16; o; o >>= 1) s += __shfl_xor_sync(0xffffffffu, s, o);
            if (lane == 0) {
                float z = s + b2j;
                if (st4 == 0) {
                    k1 = z;
                    g_ws[j2] = wcur + (h * (1.f / 3.f)) * z;
                } else if (st4 == 1) {
                    k2 = z;
                    g_ws[j2] = wcur + h * (z - k1 * (1.f / 3.f));
                } else if (st4 == 2) {
                    k3 = z;
                    g_ws[j2] = wcur + h * (k1 - k2 + z);
                } else {
                    wcur += h * 0.125f * (k1 + 3.f * (k2 + k3) + z);
                    g_w[j2] = wcur;
                }
            }
        }
        if (stage != 4 * (T_STEPS - 1) - 1) gridsync();
    }
}

// ---------------- xw: z[n] = dis[n] * (x_last[n] @ W_T) ----------------
__global__ void xw_kernel(const float* __restrict__ xlast, int n) {
    __shared__ float Ws[64 * 64];
    __shared__ float xs[64 * 64];
    int n0 = blockIdx.x * 64;
    for (int i = threadIdx.x; i < 4096; i += 256) Ws[i] = g_w[i];
    for (int i = threadIdx.x; i < 4096; i += 256) {
        int r = i >> 6, c = i & 63, nn = n0 + r;
        xs[i] = (nn < n) ? xlast[(size_t)nn * 64 + c] : 0.f;
    }
    __syncthreads();
    int tx = threadIdx.x & 15, ty = threadIdx.x >> 4;
    float acc[4][4] = {};
#pragma unroll 4
    for (int k = 0; k < 64; ++k) {
        float4 b = *(const float4*)&Ws[k * 64 + tx * 4];
#pragma unroll
        for (int i = 0; i < 4; ++i) {
            float a = xs[(ty * 4 + i) * 64 + k];
            acc[i][0] += a * b.x; acc[i][1] += a * b.y;
            acc[i][2] += a * b.z; acc[i][3] += a * b.w;
        }
    }
    float* gz = (float*)g_z4;
#pragma unroll
    for (int i = 0; i < 4; ++i) {
        int nn = n0 + ty * 4 + i;
        if (nn < n) {
            float dn = g_dis[nn];
            float4 z;
            z.x = dn * acc[i][0]; z.y = dn * acc[i][1];
            z.z = dn * acc[i][2]; z.w = dn * acc[i][3];
            *(float4*)&gz[nn * 64 + tx * 4] = z;
        }
    }
}

// ---------------- gather: acc[c] = dis[c] * (z[c] + sum_in z[src]) ----------------
// warp per node; pure coalesced L2 reads, no atomics
__global__ void gather_kernel(int n) {
    int gw   = (blockIdx.x * 256 + threadIdx.x) >> 5;
    int lane = threadIdx.x & 31;
    if (gw >= n) return;
    int k0 = g_base[gw], k1 = g_base[gw + 1];
    const float* __restrict__ z = (const float*)g_z4;
    float s0 = z[(size_t)gw * 64 + lane];
    float s1 = z[(size_t)gw * 64 + 32 + lane];
    for (int kb = k0; kb < k1; kb += 32) {
        int m = k1 - kb; if (m > 32) m = 32;
        int rl = (lane < m) ? __ldg(&g_src[kb + lane]) : 0;
#pragma unroll 4
        for (int j = 0; j < m; ++j) {
            int r = __shfl_sync(0xffffffffu, rl, j);
            s0 += __ldg(&z[(size_t)r * 64 + lane]);
            s1 += __ldg(&z[(size_t)r * 64 + 32 + lane]);
        }
    }
    float dc = g_dis[gw];
    float* acc = (float*)g_acc4;
    acc[(size_t)gw * 64 + lane]      = dc * s0;
    acc[(size_t)gw * 64 + 32 + lane] = dc * s1;
}

// ---------------- hA/hB fused: h = relu(acc); hA = h@W[0:64]+b1; hB = h@W[64:128] ----------------
__global__ void hab_kernel(const float* __restrict__ mw1, const float* __restrict__ mb1,
                           int n) {
    __shared__ float Ws[64 * 64];
    __shared__ float xs[64 * 64];
    const float* ga = (const float*)g_acc4;
    int n0 = blockIdx.x * 64;
    for (int i = threadIdx.x; i < 4096; i += 256) {
        int r = i >> 6, c = i & 63, nn = n0 + r;
        xs[i] = (nn < n) ? fmaxf(ga[nn * 64 + c], 0.f) : 0.f;
    }
    int tx = threadIdx.x & 15, ty = threadIdx.x >> 4;
#pragma unroll
    for (int sel = 0; sel < 2; ++sel) {
        __syncthreads();
        for (int i = threadIdx.x; i < 4096; i += 256) Ws[i] = mw1[sel * 4096 + i];
        __syncthreads();
        float acc[4][4] = {};
#pragma unroll 4
        for (int k = 0; k < 64; ++k) {
            float4 b = *(const float4*)&Ws[k * 64 + tx * 4];
#pragma unroll
            for (int i = 0; i < 4; ++i) {
                float a = xs[(ty * 4 + i) * 64 + k];
                acc[i][0] += a * b.x; acc[i][1] += a * b.y;
                acc[i][2] += a * b.z; acc[i][3] += a * b.w;
            }
        }
        float4 bb = make_float4(0.f, 0.f, 0.f, 0.f);
        if (sel == 0) {
            bb.x = mb1[tx * 4 + 0]; bb.y = mb1[tx * 4 + 1];
            bb.z = mb1[tx * 4 + 2]; bb.w = mb1[tx * 4 + 3];
        }
        float* out = sel ? (float*)g_hB4 : (float*)g_hA4;
#pragma unroll
        for (int i = 0; i < 4; ++i) {
            int nn = n0 + ty * 4 + i;
            if (nn < n) {
                float4 v;
                v.x = acc[i][0] + bb.x; v.y = acc[i][1] + bb.y;
                v.z = acc[i][2] + bb.z; v.w = acc[i][3] + bb.w;
                *(float4*)&out[nn * 64 + tx * 4] = v;
            }
        }
    }
}

// ---------------- edge MLP: out[e] = relu(hA[r]+hB[c]+ea@C) . w2 + b2 ----------------
__global__ void edge_kernel(const float* __restrict__ ea, const int* __restrict__ ei,
                            const float* __restrict__ mw1, const float* __restrict__ w2,
                            const float* __restrict__ b2, float* __restrict__ out, int e) {
    __shared__ float Cs[16 * 64];
    __shared__ float w2s[64];
    for (int i = threadIdx.x; i < 1024; i += 256) Cs[i] = mw1[128 * 64 + i];
    if (threadIdx.x < 64) w2s[threadIdx.x] = w2[threadIdx.x];
    __syncthreads();
    int warp = threadIdx.x >> 5, lane = threadIdx.x & 31;
    int eg = blockIdx.x * 8 + warp;
    if (eg >= e) return;
    const float* hA = (const float*)g_hA4;
    const float* hB = (const float*)g_hB4;
    int r = __ldg(&ei[eg]);
    int c = __ldg(&ei[e + eg]);
    float av = (lane < 16) ? __ldg(&ea[(size_t)eg * 16 + lane]) : 0.f;
    int j0 = lane, j1 = lane + 32;
    float s0 = hA[r * 64 + j0] + hB[c * 64 + j0];
    float s1 = hA[r * 64 + j1] + hB[c * 64 + j1];
#pragma unroll
    for (int f = 0; f < 16; ++f) {
        float a = __shfl_sync(0xffffffffu, av, f);
        s0 += a * Cs[f * 64 + j0];
        s1 += a * Cs[f * 64 + j1];
    }
    float p = fmaxf(s0, 0.f) * w2s[j0] + fmaxf(s1, 0.f) * w2s[j1];
#pragma unroll
    for (int o = 16; o; o >>= 1) p += __shfl_xor_sync(0xffffffffu, p, o);
    if (lane == 0) out[eg] = p + b2[0];
}

// ---------------- launcher ----------------
extern "C" void kernel_launch(void* const* d_in, const int* in_sizes, int n_in,
                              void* d_out, int out_size) {
    const float* x_seq = (const float*)d_in[0];
    const float* ea    = (const float*)d_in[1];
    const float* iw    = (const float*)d_in[2];
    const float* W1    = (const float*)d_in[3];
    const float* b1o   = (const float*)d_in[4];
    const float* W2    = (const float*)d_in[5];
    const float* b2o   = (const float*)d_in[6];
    const float* mw1   = (const float*)d_in[7];
    const float* mb1   = (const float*)d_in[8];
    const float* mw2   = (const float*)d_in[9];
    const float* mb2   = (const float*)d_in[10];
    const int*   ei    = (const int*)d_in[11];
    float* out = (float*)d_out;

    const int n = NN;
    const int e = EE;
    const float* xlast = x_seq + (size_t)(T_STEPS - 1) * n * 64;
    const float h = 1.0f / (float)(T_STEPS - 1);

    cudaFuncSetAttribute(ode_persist, cudaFuncAttributeMaxDynamicSharedMemorySize,
                         ODE_SMEM_FLOATS * 4);

    // CSR build + normalization (independent of ODE)
    init_kernel<<<(n + 255) / 256, 256>>>(iw, n);
    count_kernel<<<(e + 255) / 256, 256>>>(ei, e);
    dis_kernel<<<(n + 255) / 256, 256>>>(n);
    scan1_kernel<<<NB_SCAN, 1024>>>(n);
    scan2_kernel<<<1, 128>>>(NB_SCAN);
    scan3_kernel<<<NB_SCAN, 1024>>>(n);
    place_kernel<<<(e + 255) / 256, 256>>>(ei, e);

    // one-time weight transposes for contiguous GEMV rows
    {
        float* w1t; cudaGetSymbolAddress((void**)&w1t, g_W1t);
        float* w2t; cudaGetSymbolAddress((void**)&w2t, g_W2t);
        dim3 t1g(BN / 32, FLAT / 32);
        transpose_kernel<<<t1g, dim3(32, 8)>>>(W1, w1t, FLAT, BN);
        dim3 t2g(FLAT / 32, BN / 32);
        transpose_kernel<<<t2g, dim3(32, 8)>>>(W2, w2t, BN, FLAT);
    }

    // full weight ODE in one persistent kernel
    ode_persist<<<NB_ODE, 1024, ODE_SMEM_FLOATS * 4>>>(b1o, b2o, h);

    // GCN: dense part, then atomic-free gather
    xw_kernel<<<(n + 63) / 64, 256>>>(xlast, n);
    gather_kernel<<<(n * 32 + 255) / 256, 256>>>(n);

    // node-side halves of the edge MLP first layer
    hab_kernel<<<(n + 63) / 64, 256>>>(mw1, mb1, n);

    // per-edge MLP
    edge_kernel<<<(e + 7) / 8, 256>>>(ea, ei, mw1, mw2, mb2, out, e);
}

// round 5
// speedup vs baseline: 1.8248x; 1.4438x over previous
#include <cuda_runtime.h>

// Problem constants (fixed by the dataset)
#define T_STEPS 8
#define NN      100000
#define EE      1600000
#define FLAT    4096    // 64*64
#define BN      1024    // bottleneck
#define NB_ODE  128     // persistent ODE grid (1 block/SM, co-resident)
#define NB_SCAN 98      // ceil(NN/1024)
#define EPB     64      // edges per block in edge_kernel

// ---------------- device scratch (no allocs allowed) ----------------
__device__ float  g_w[FLAT];
__device__ float  g_ws[FLAT];
__device__ float  g_t[BN];
__device__ float  g_W1t[BN * FLAT];   // transposed: row j (1024 rows) x k (4096)
__device__ float  g_W2t[FLAT * BN];   // transposed: row j (4096 rows) x k (1024)
__device__ unsigned g_barcnt;
__device__ float  g_dis[NN];
__device__ int    g_cnt[NN];        // in-degree (no self)
__device__ int    g_base[NN + 1];   // CSR row offsets (by destination)
__device__ int    g_cur[NN];        // placement cursors
__device__ int    g_src[EE];        // CSR: source node per in-edge
__device__ int    g_bsum[NB_SCAN];
__device__ int    g_boff[NB_SCAN];
__device__ float4 g_z4[NN * 16];    // dis[n] * (x W_T)   [N,64]
__device__ float4 g_acc4[NN * 16];  // aggregated messages [N,64]
__device__ float4 g_hA4[NN * 16];   // h @ A + b1          [N,64]
__device__ float4 g_hB4[NN * 16];   // h @ B               [N,64]

// ---------------- init: copy w0, zero counters, reset barrier ----------------
__global__ void init_kernel(const float* __restrict__ iw, int n) {
    int i = blockIdx.x * 256 + threadIdx.x;
    if (i == 0) g_barcnt = 0u;
    if (i < FLAT) g_w[i] = iw[i];
    if (i < n)    g_cnt[i] = 0;
}

// ---------------- in-degree count ----------------
__global__ void count_kernel(const int* __restrict__ ei, int e) {
    int i = blockIdx.x * 256 + threadIdx.x;
    if (i < e) atomicAdd(&g_cnt[ei[e + i]], 1);
}

// ---------------- dis = rsqrt(deg), deg = cnt + 1 (self loop) ----------------
__global__ void dis_kernel(int n) {
    int i = blockIdx.x * 256 + threadIdx.x;
    if (i < n) g_dis[i] = rsqrtf(1.0f + (float)g_cnt[i]);
}

// ---------------- CSR offset scan (3 small kernels) ----------------
__global__ void scan1_kernel(int n) {            // block sums
    __shared__ int sm_[1024];
    int i = blockIdx.x * 1024 + threadIdx.x;
    sm_[threadIdx.x] = (i < n) ? g_cnt[i] : 0;
    __syncthreads();
#pragma unroll
    for (int o = 512; o; o >>= 1) {
        if (threadIdx.x < o) sm_[threadIdx.x] += sm_[threadIdx.x + o];
        __syncthreads();
    }
    if (threadIdx.x == 0) g_bsum[blockIdx.x] = sm_[0];
}

__global__ void scan2_kernel(int nb) {           // serial scan of block sums
    __shared__ int sb[NB_SCAN];
    if (threadIdx.x < nb) sb[threadIdx.x] = g_bsum[threadIdx.x];
    __syncthreads();
    if (threadIdx.x == 0) {
        int run = 0;
        for (int b = 0; b < nb; ++b) { g_boff[b] = run; run += sb[b]; }
        g_base[NN] = run;            // == EE
    }
}

__global__ void scan3_kernel(int n) {            // in-block exclusive scan + offset
    __shared__ int sm_[1024];
    int i = blockIdx.x * 1024 + threadIdx.x;
    int v = (i < n) ? g_cnt[i] : 0;
    sm_[threadIdx.x] = v;
    __syncthreads();
#pragma unroll
    for (int o = 1; o < 1024; o <<= 1) {         // Hillis-Steele inclusive
        int t = (threadIdx.x >= o) ? sm_[threadIdx.x - o] : 0;
        __syncthreads();
        sm_[threadIdx.x] += t;
        __syncthreads();
    }
    if (i < n) {
        int excl = sm_[threadIdx.x] - v + g_boff[blockIdx.x];
        g_base[i] = excl;
        g_cur[i]  = excl;
    }
}

// ---------------- CSR placement ----------------
__global__ void place_kernel(const int* __restrict__ ei, int e) {
    int i = blockIdx.x * 256 + threadIdx.x;
    if (i < e) {
        int c = ei[e + i];
        int p = atomicAdd(&g_cur[c], 1);
        g_src[p] = ei[i];
    }
}

// ---------------- 32x32 tiled transpose: dst[C][R] = src[R][C]^T ----------------
__global__ void transpose_kernel(const float* __restrict__ src, float* __restrict__ dst,
                                 int R, int C) {
    __shared__ float tile[32][33];
    int bx = blockIdx.x * 32, by = blockIdx.y * 32;
    int x = bx + threadIdx.x;
#pragma unroll
    for (int i = 0; i < 32; i += 8) {
        int y = by + threadIdx.y + i;
        tile[threadIdx.y + i][threadIdx.x] = src[(size_t)y * C + x];
    }
    __syncthreads();
    int x2 = by + threadIdx.x;
#pragma unroll
    for (int i = 0; i < 32; i += 8) {
        int y2 = bx + threadIdx.y + i;
        dst[(size_t)y2 * R + x2] = tile[threadIdx.x][threadIdx.y + i];
    }
}

// ---------------- fast grid barrier: monotonic counter, acquire/release ----------------
__device__ __forceinline__ void gridsync(unsigned target) {
    __syncthreads();
    if (threadIdx.x == 0) {
        asm volatile("red.add.release.gpu.u32 [%0], %1;"
                     :: "l"(&g_barcnt), "r"(1u) : "memory");
        unsigned v;
        do {
            asm volatile("ld.acquire.gpu.u32 %0, [%1];"
                         : "=r"(v) : "l"(&g_barcnt) : "memory");
        } while (v < target);
    }
    __syncthreads();
}

// ---------------- persistent ODE ----------------
#define ODE_SMEM_FLOATS (32768 + 4096 + 1024 + 32)

__global__ __launch_bounds__(1024, 1)
void ode_persist(const float* __restrict__ b1, const float* __restrict__ b2, float h) {
    extern __shared__ float sm[];
    float* sW1 = sm;
    float* sw  = sm + 32768;
    float* st  = sm + 32768 + 4096;
    float* red = sm + 32768 + 4096 + 1024;   // [8 groups][4 warps]

    const int tid  = threadIdx.x;
    const int b    = blockIdx.x;
    const int lane = tid & 31;
    const int wid  = tid >> 5;
    const int grp  = tid >> 7;
    const int tin  = tid & 127;
    const int wgrp = tin >> 5;

    {
        const float4* src = (const float4*)(g_W1t + ((size_t)b * 8) * 4096);
        float4* dst = (float4*)sW1;
#pragma unroll
        for (int i = 0; i < 8; ++i) dst[tid + 1024 * i] = src[tid + 1024 * i];
    }
    float4 w2r[8];
    {
        const float4* src = (const float4*)(g_W2t + ((size_t)(b * 32 + wid)) * 1024);
#pragma unroll
        for (int i = 0; i < 8; ++i) w2r[i] = src[lane + 32 * i];
    }
    const int   j2  = b * 32 + wid;
    const float b2j = b2[j2];
    float wcur = g_w[j2];
    float k1 = 0.f, k2 = 0.f, k3 = 0.f;
    unsigned tgt = 0;
    __syncthreads();

    for (int stage = 0; stage < 4 * (T_STEPS - 1); ++stage) {
        const int st4 = stage & 3;
        {
            const float4* win = (const float4*)(st4 == 0 ? g_w : g_ws);
            ((float4*)sw)[tid] = __ldcg(win + tid);
        }
        __syncthreads();

        {
            const float4* wrow = (const float4*)(sW1 + (size_t)grp * 4096);
            const float4* sw4  = (const float4*)sw;
            float s = 0.f;
#pragma unroll
            for (int i = 0; i < 8; ++i) {
                float4 a = wrow[tin + 128 * i];
                float4 v = sw4[tin + 128 * i];
                s += a.x * v.x + a.y * v.y + a.z * v.z + a.w * v.w;
            }
#pragma unroll
            for (int o = 16; o; o >>= 1) s += __shfl_xor_sync(0xffffffffu, s, o);
            if (lane == 0) red[grp * 4 + wgrp] = s;
        }
        __syncthreads();
        if (tid < 8) {
            float tot = red[tid * 4] + red[tid * 4 + 1] + red[tid * 4 + 2] + red[tid * 4 + 3];
            g_t[b * 8 + tid] = tanhf(tot + b1[b * 8 + tid]);
        }
        tgt += NB_ODE;
        gridsync(tgt);

        if (tid < 256) ((float4*)st)[tid] = __ldcg(((const float4*)g_t) + tid);
        __syncthreads();
        {
            const float4* st4p = (const float4*)st;
            float s = 0.f;
#pragma unroll
            for (int i = 0; i < 8; ++i) {
                float4 a = w2r[i];
                float4 v = st4p[lane + 32 * i];
                s += a.x * v.x + a.y * v.y + a.z * v.z + a.w * v.w;
            }
#pragma unroll
            for (int o = 16; o; o >>= 1) s += __shfl_xor_sync(0xffffffffu, s, o);
            if (lane == 0) {
                float z = s + b2j;
                if (st4 == 0) {
                    k1 = z;
                    g_ws[j2] = wcur + (h * (1.f / 3.f)) * z;
                } else if (st4 == 1) {
                    k2 = z;
                    g_ws[j2] = wcur + h * (z - k1 * (1.f / 3.f));
                } else if (st4 == 2) {
                    k3 = z;
                    g_ws[j2] = wcur + h * (k1 - k2 + z);
                } else {
                    wcur += h * 0.125f * (k1 + 3.f * (k2 + k3) + z);
                    g_w[j2] = wcur;
                }
            }
        }
        if (stage != 4 * (T_STEPS - 1) - 1) {
            tgt += NB_ODE;
            gridsync(tgt);
        }
    }
}

// ---------------- xw: z[n] = dis[n] * (x_last[n] @ W_T) ----------------
__global__ void xw_kernel(const float* __restrict__ xlast, int n) {
    __shared__ float Ws[64 * 64];
    __shared__ float xs[64 * 64];
    int n0 = blockIdx.x * 64;
    for (int i = threadIdx.x; i < 4096; i += 256) Ws[i] = g_w[i];
    for (int i = threadIdx.x; i < 4096; i += 256) {
        int r = i >> 6, c = i & 63, nn = n0 + r;
        xs[i] = (nn < n) ? xlast[(size_t)nn * 64 + c] : 0.f;
    }
    __syncthreads();
    int tx = threadIdx.x & 15, ty = threadIdx.x >> 4;
    float acc[4][4] = {};
#pragma unroll 4
    for (int k = 0; k < 64; ++k) {
        float4 b = *(const float4*)&Ws[k * 64 + tx * 4];
#pragma unroll
        for (int i = 0; i < 4; ++i) {
            float a = xs[(ty * 4 + i) * 64 + k];
            acc[i][0] += a * b.x; acc[i][1] += a * b.y;
            acc[i][2] += a * b.z; acc[i][3] += a * b.w;
        }
    }
    float* gz = (float*)g_z4;
#pragma unroll
    for (int i = 0; i < 4; ++i) {
        int nn = n0 + ty * 4 + i;
        if (nn < n) {
            float dn = g_dis[nn];
            float4 z;
            z.x = dn * acc[i][0]; z.y = dn * acc[i][1];
            z.z = dn * acc[i][2]; z.w = dn * acc[i][3];
            *(float4*)&gz[nn * 64 + tx * 4] = z;
        }
    }
}

// ---------------- gather: acc[c] = dis[c] * (z[c] + sum_in z[src]) ----------------
__global__ void gather_kernel(int n) {
    int gw   = (blockIdx.x * 256 + threadIdx.x) >> 5;
    int lane = threadIdx.x & 31;
    if (gw >= n) return;
    int k0 = g_base[gw], k1 = g_base[gw + 1];
    const float* __restrict__ z = (const float*)g_z4;
    float s0 = z[(size_t)gw * 64 + lane];
    float s1 = z[(size_t)gw * 64 + 32 + lane];
    for (int kb = k0; kb < k1; kb += 32) {
        int m = k1 - kb; if (m > 32) m = 32;
        int rl = (lane < m) ? __ldg(&g_src[kb + lane]) : 0;
#pragma unroll 4
        for (int j = 0; j < m; ++j) {
            int r = __shfl_sync(0xffffffffu, rl, j);
            s0 += __ldg(&z[(size_t)r * 64 + lane]);
            s1 += __ldg(&z[(size_t)r * 64 + 32 + lane]);
        }
    }
    float dc = g_dis[gw];
    float* acc = (float*)g_acc4;
    acc[(size_t)gw * 64 + lane]      = dc * s0;
    acc[(size_t)gw * 64 + 32 + lane] = dc * s1;
}

// ---------------- hA/hB fused: h = relu(acc); hA = h@W[0:64]+b1; hB = h@W[64:128] ----------------
__global__ void hab_kernel(const float* __restrict__ mw1, const float* __restrict__ mb1,
                           int n) {
    __shared__ float Ws[64 * 64];
    __shared__ float xs[64 * 64];
    const float* ga = (const float*)g_acc4;
    int n0 = blockIdx.x * 64;
    for (int i = threadIdx.x; i < 4096; i += 256) {
        int r = i >> 6, c = i & 63, nn = n0 + r;
        xs[i] = (nn < n) ? fmaxf(ga[nn * 64 + c], 0.f) : 0.f;
    }
    int tx = threadIdx.x & 15, ty = threadIdx.x >> 4;
#pragma unroll
    for (int sel = 0; sel < 2; ++sel) {
        __syncthreads();
        for (int i = threadIdx.x; i < 4096; i += 256) Ws[i] = mw1[sel * 4096 + i];
        __syncthreads();
        float acc[4][4] = {};
#pragma unroll 4
        for (int k = 0; k < 64; ++k) {
            float4 b = *(const float4*)&Ws[k * 64 + tx * 4];
#pragma unroll
            for (int i = 0; i < 4; ++i) {
                float a = xs[(ty * 4 + i) * 64 + k];
                acc[i][0] += a * b.x; acc[i][1] += a * b.y;
                acc[i][2] += a * b.z; acc[i][3] += a * b.w;
            }
        }
        float4 bb = make_float4(0.f, 0.f, 0.f, 0.f);
        if (sel == 0) {
            bb.x = mb1[tx * 4 + 0]; bb.y = mb1[tx * 4 + 1];
            bb.z = mb1[tx * 4 + 2]; bb.w = mb1[tx * 4 + 3];
        }
        float* out = sel ? (float*)g_hB4 : (float*)g_hA4;
#pragma unroll
        for (int i = 0; i < 4; ++i) {
            int nn = n0 + ty * 4 + i;
            if (nn < n) {
                float4 v;
                v.x = acc[i][0] + bb.x; v.y = acc[i][1] + bb.y;
                v.z = acc[i][2] + bb.z; v.w = acc[i][3] + bb.w;
                *(float4*)&out[nn * 64 + tx * 4] = v;
            }
        }
    }
}

// ---------------- edge MLP: out[e] = relu(hA[r]+hB[c]+ea@C) . w2 + b2 ----------------
// block = 256 threads / 64 edges; C columns in registers, ea staged in smem
__global__ __launch_bounds__(256)
void edge_kernel(const float* __restrict__ ea, const int* __restrict__ ei,
                 const float* __restrict__ mw1, const float* __restrict__ w2,
                 const float* __restrict__ b2, float* __restrict__ out, int e) {
    __shared__ float4 sea[EPB * 4];
    __shared__ int   sr[EPB], sc[EPB];
    __shared__ float sout[EPB];
    const int tid  = threadIdx.x;
    const int lane = tid & 31;
    const int warp = tid >> 5;
    const int e0   = blockIdx.x * EPB;
    const int valid = (e - e0 < EPB) ? (e - e0) : EPB;

    // edge-invariant operands -> registers (once per block)
    float c0[16], c1[16];
#pragma unroll
    for (int f = 0; f < 16; ++f) {
        c0[f] = __ldg(&mw1[(128 + f) * 64 + lane]);
        c1[f] = __ldg(&mw1[(128 + f) * 64 + lane + 32]);
    }
    const float w20 = __ldg(&w2[lane]);
    const float w21 = __ldg(&w2[lane + 32]);
    const float bb  = __ldg(&b2[0]);

    // stage ea (float4) + indices
    if (tid < valid * 4) sea[tid] = ((const float4*)(ea + (size_t)e0 * 16))[tid];
    if (tid < valid)                sr[tid]       = __ldg(&ei[e0 + tid]);
    else if (tid >= EPB && tid < EPB + valid) sc[tid - EPB] = __ldg(&ei[e + e0 + (tid - EPB)]);
    __syncthreads();

    const float* __restrict__ hA = (const float*)g_hA4;
    const float* __restrict__ hB = (const float*)g_hB4;
#pragma unroll
    for (int it = 0; it < 8; ++it) {
        int le = warp * 8 + it;
        if (le < valid) {
            int r = sr[le], c = sc[le];
            float s0 = hA[(size_t)r * 64 + lane]      + hB[(size_t)c * 64 + lane];
            float s1 = hA[(size_t)r * 64 + 32 + lane] + hB[(size_t)c * 64 + 32 + lane];
#pragma unroll
            for (int q = 0; q < 4; ++q) {
                float4 a = sea[le * 4 + q];
                s0 += a.x * c0[4 * q] + a.y * c0[4 * q + 1] + a.z * c0[4 * q + 2] + a.w * c0[4 * q + 3];
                s1 += a.x * c1[4 * q] + a.y * c1[4 * q + 1] + a.z * c1[4 * q + 2] + a.w * c1[4 * q + 3];
            }
            float p = fmaxf(s0, 0.f) * w20 + fmaxf(s1, 0.f) * w21;
#pragma unroll
            for (int o = 16; o; o >>= 1) p += __shfl_xor_sync(0xffffffffu, p, o);
            if (lane == 0) sout[le] = p + bb;
        }
    }
    __syncthreads();
    if (tid < valid) out[e0 + tid] = sout[tid];
}

// ---------------- launcher ----------------
extern "C" void kernel_launch(void* const* d_in, const int* in_sizes, int n_in,
                              void* d_out, int out_size) {
    const float* x_seq = (const float*)d_in[0];
    const float* ea    = (const float*)d_in[1];
    const float* iw    = (const float*)d_in[2];
    const float* W1    = (const float*)d_in[3];
    const float* b1o   = (const float*)d_in[4];
    const float* W2    = (const float*)d_in[5];
    const float* b2o   = (const float*)d_in[6];
    const float* mw1   = (const float*)d_in[7];
    const float* mb1   = (const float*)d_in[8];
    const float* mw2   = (const float*)d_in[9];
    const float* mb2   = (const float*)d_in[10];
    const int*   ei    = (const int*)d_in[11];
    float* out = (float*)d_out;

    const int n = NN;
    const int e = EE;
    const float* xlast = x_seq + (size_t)(T_STEPS - 1) * n * 64;
    const float h = 1.0f / (float)(T_STEPS - 1);

    cudaFuncSetAttribute(ode_persist, cudaFuncAttributeMaxDynamicSharedMemorySize,
                         ODE_SMEM_FLOATS * 4);

    // init + transposes + ODE first (puts ode_persist early for ncu attribution)
    init_kernel<<<(n + 255) / 256, 256>>>(iw, n);
    {
        float* w1t; cudaGetSymbolAddress((void**)&w1t, g_W1t);
        float* w2t; cudaGetSymbolAddress((void**)&w2t, g_W2t);
        dim3 t1g(BN / 32, FLAT / 32);
        transpose_kernel<<<t1g, dim3(32, 8)>>>(W1, w1t, FLAT, BN);
        dim3 t2g(FLAT / 32, BN / 32);
        transpose_kernel<<<t2g, dim3(32, 8)>>>(W2, w2t, BN, FLAT);
    }
    ode_persist<<<NB_ODE, 1024, ODE_SMEM_FLOATS * 4>>>(b1o, b2o, h);

    // CSR build + normalization (independent of ODE result)
    count_kernel<<<(e + 255) / 256, 256>>>(ei, e);
    dis_kernel<<<(n + 255) / 256, 256>>>(n);
    scan1_kernel<<<NB_SCAN, 1024>>>(n);
    scan2_kernel<<<1, 128>>>(NB_SCAN);
    scan3_kernel<<<NB_SCAN, 1024>>>(n);
    place_kernel<<<(e + 255) / 256, 256>>>(ei, e);

    // GCN: dense part, then atomic-free gather
    xw_kernel<<<(n + 63) / 64, 256>>>(xlast, n);
    gather_kernel<<<(n * 32 + 255) / 256, 256>>>(n);

    // node-side halves of the edge MLP first layer
    hab_kernel<<<(n + 63) / 64, 256>>>(mw1, mb1, n);

    // per-edge MLP
    edge_kernel<<<(e + EPB - 1) / EPB, 256>>>(ea, ei, mw1, mw2, mb2, out, e);
}

// round 6
// speedup vs baseline: 1.8642x; 1.0216x over previous
#include <cuda_runtime.h>
#include <cuda_fp16.h>

// Problem constants (fixed by the dataset)
#define T_STEPS 8
#define NN      100000
#define EE      1600000
#define FLAT    4096    // 64*64
#define BN      1024    // bottleneck
#define NB_ODE  128     // persistent ODE grid (1 block/SM, co-resident)
#define NB_SCAN 98      // ceil(NN/1024)
#define EPB     64      // edges per block in edge_kernel

// ---------------- device scratch (no allocs allowed) ----------------
__device__ float  g_w[FLAT];
__device__ float  g_ws[FLAT];
__device__ float  g_t[BN];
__device__ float  g_W1t[BN * FLAT];   // transposed: row j (1024 rows) x k (4096)
__device__ float  g_W2t[FLAT * BN];   // transposed: row j (4096 rows) x k (1024)
__device__ unsigned g_barcnt;
__device__ float  g_dis[NN];
__device__ int    g_cnt[NN];        // in-degree (no self)
__device__ int    g_base[NN + 1];   // CSR row offsets (by destination)
__device__ int    g_cur[NN];        // placement cursors
__device__ int    g_src[EE];        // CSR: source node per in-edge
__device__ int    g_bsum[NB_SCAN];
__device__ int    g_boff[NB_SCAN];
__device__ __align__(16) __half2 g_zh[NN * 32];   // dis[n]*(x W_T)  fp16 [N,64]
__device__ float4 g_acc4[NN * 16];                 // aggregated msgs  [N,64]
__device__ __align__(16) __half2 g_hAh[NN * 32];  // h@A+b1 fp16      [N,64]
__device__ __align__(16) __half2 g_hBh[NN * 32];  // h@B    fp16      [N,64]

// ---------------- init: copy w0, zero counters, reset barrier ----------------
__global__ void init_kernel(const float* __restrict__ iw, int n) {
    int i = blockIdx.x * 256 + threadIdx.x;
    if (i == 0) g_barcnt = 0u;
    if (i < FLAT) g_w[i] = iw[i];
    if (i < n)    g_cnt[i] = 0;
}

// ---------------- in-degree count ----------------
__global__ void count_kernel(const int* __restrict__ ei, int e) {
    int i = blockIdx.x * 256 + threadIdx.x;
    if (i < e) atomicAdd(&g_cnt[ei[e + i]], 1);
}

// ---------------- dis = rsqrt(deg), deg = cnt + 1 (self loop) ----------------
__global__ void dis_kernel(int n) {
    int i = blockIdx.x * 256 + threadIdx.x;
    if (i < n) g_dis[i] = rsqrtf(1.0f + (float)g_cnt[i]);
}

// ---------------- CSR offset scan (3 small kernels) ----------------
__global__ void scan1_kernel(int n) {            // block sums
    __shared__ int sm_[1024];
    int i = blockIdx.x * 1024 + threadIdx.x;
    sm_[threadIdx.x] = (i < n) ? g_cnt[i] : 0;
    __syncthreads();
#pragma unroll
    for (int o = 512; o; o >>= 1) {
        if (threadIdx.x < o) sm_[threadIdx.x] += sm_[threadIdx.x + o];
        __syncthreads();
    }
    if (threadIdx.x == 0) g_bsum[blockIdx.x] = sm_[0];
}

__global__ void scan2_kernel(int nb) {           // serial scan of block sums
    __shared__ int sb[NB_SCAN];
    if (threadIdx.x < nb) sb[threadIdx.x] = g_bsum[threadIdx.x];
    __syncthreads();
    if (threadIdx.x == 0) {
        int run = 0;
        for (int b = 0; b < nb; ++b) { g_boff[b] = run; run += sb[b]; }
        g_base[NN] = run;            // == EE
    }
}

__global__ void scan3_kernel(int n) {            // in-block exclusive scan + offset
    __shared__ int sm_[1024];
    int i = blockIdx.x * 1024 + threadIdx.x;
    int v = (i < n) ? g_cnt[i] : 0;
    sm_[threadIdx.x] = v;
    __syncthreads();
#pragma unroll
    for (int o = 1; o < 1024; o <<= 1) {         // Hillis-Steele inclusive
        int t = (threadIdx.x >= o) ? sm_[threadIdx.x - o] : 0;
        __syncthreads();
        sm_[threadIdx.x] += t;
        __syncthreads();
    }
    if (i < n) {
        int excl = sm_[threadIdx.x] - v + g_boff[blockIdx.x];
        g_base[i] = excl;
        g_cur[i]  = excl;
    }
}

// ---------------- CSR placement ----------------
__global__ void place_kernel(const int* __restrict__ ei, int e) {
    int i = blockIdx.x * 256 + threadIdx.x;
    if (i < e) {
        int c = ei[e + i];
        int p = atomicAdd(&g_cur[c], 1);
        g_src[p] = ei[i];
    }
}

// ---------------- 32x32 tiled transpose: dst[C][R] = src[R][C]^T ----------------
__global__ void transpose_kernel(const float* __restrict__ src, float* __restrict__ dst,
                                 int R, int C) {
    __shared__ float tile[32][33];
    int bx = blockIdx.x * 32, by = blockIdx.y * 32;
    int x = bx + threadIdx.x;
#pragma unroll
    for (int i = 0; i < 32; i += 8) {
        int y = by + threadIdx.y + i;
        tile[threadIdx.y + i][threadIdx.x] = src[(size_t)y * C + x];
    }
    __syncthreads();
    int x2 = by + threadIdx.x;
#pragma unroll
    for (int i = 0; i < 32; i += 8) {
        int y2 = bx + threadIdx.y + i;
        dst[(size_t)y2 * R + x2] = tile[threadIdx.x][threadIdx.y + i];
    }
}

// ---------------- fast grid barrier: monotonic counter, acquire/release ----------------
__device__ __forceinline__ void gridsync(unsigned target) {
    __syncthreads();
    if (threadIdx.x == 0) {
        asm volatile("red.add.release.gpu.u32 [%0], %1;"
                     :: "l"(&g_barcnt), "r"(1u) : "memory");
        unsigned v;
        do {
            asm volatile("ld.acquire.gpu.u32 %0, [%1];"
                         : "=r"(v) : "l"(&g_barcnt) : "memory");
        } while (v < target);
    }
    __syncthreads();
}

// ---------------- persistent ODE (unchanged) ----------------
#define ODE_SMEM_FLOATS (32768 + 4096 + 1024 + 32)

__global__ __launch_bounds__(1024, 1)
void ode_persist(const float* __restrict__ b1, const float* __restrict__ b2, float h) {
    extern __shared__ float sm[];
    float* sW1 = sm;
    float* sw  = sm + 32768;
    float* st  = sm + 32768 + 4096;
    float* red = sm + 32768 + 4096 + 1024;   // [8 groups][4 warps]

    const int tid  = threadIdx.x;
    const int b    = blockIdx.x;
    const int lane = tid & 31;
    const int wid  = tid >> 5;
    const int grp  = tid >> 7;
    const int tin  = tid & 127;
    const int wgrp = tin >> 5;

    {
        const float4* src = (const float4*)(g_W1t + ((size_t)b * 8) * 4096);
        float4* dst = (float4*)sW1;
#pragma unroll
        for (int i = 0; i < 8; ++i) dst[tid + 1024 * i] = src[tid + 1024 * i];
    }
    float4 w2r[8];
    {
        const float4* src = (const float4*)(g_W2t + ((size_t)(b * 32 + wid)) * 1024);
#pragma unroll
        for (int i = 0; i < 8; ++i) w2r[i] = src[lane + 32 * i];
    }
    const int   j2  = b * 32 + wid;
    const float b2j = b2[j2];
    float wcur = g_w[j2];
    float k1 = 0.f, k2 = 0.f, k3 = 0.f;
    unsigned tgt = 0;
    __syncthreads();

    for (int stage = 0; stage < 4 * (T_STEPS - 1); ++stage) {
        const int st4 = stage & 3;
        {
            const float4* win = (const float4*)(st4 == 0 ? g_w : g_ws);
            ((float4*)sw)[tid] = __ldcg(win + tid);
        }
        __syncthreads();

        {
            const float4* wrow = (const float4*)(sW1 + (size_t)grp * 4096);
            const float4* sw4  = (const float4*)sw;
            float s = 0.f;
#pragma unroll
            for (int i = 0; i < 8; ++i) {
                float4 a = wrow[tin + 128 * i];
                float4 v = sw4[tin + 128 * i];
                s += a.x * v.x + a.y * v.y + a.z * v.z + a.w * v.w;
            }
#pragma unroll
            for (int o = 16; o; o >>= 1) s += __shfl_xor_sync(0xffffffffu, s, o);
            if (lane == 0) red[grp * 4 + wgrp] = s;
        }
        __syncthreads();
        if (tid < 8) {
            float tot = red[tid * 4] + red[tid * 4 + 1] + red[tid * 4 + 2] + red[tid * 4 + 3];
            g_t[b * 8 + tid] = tanhf(tot + b1[b * 8 + tid]);
        }
        tgt += NB_ODE;
        gridsync(tgt);

        if (tid < 256) ((float4*)st)[tid] = __ldcg(((const float4*)g_t) + tid);
        __syncthreads();
        {
            const float4* st4p = (const float4*)st;
            float s = 0.f;
#pragma unroll
            for (int i = 0; i < 8; ++i) {
                float4 a = w2r[i];
                float4 v = st4p[lane + 32 * i];
                s += a.x * v.x + a.y * v.y + a.z * v.z + a.w * v.w;
            }
#pragma unroll
            for (int o = 16; o; o >>= 1) s += __shfl_xor_sync(0xffffffffu, s, o);
            if (lane == 0) {
                float z = s + b2j;
                if (st4 == 0) {
                    k1 = z;
                    g_ws[j2] = wcur + (h * (1.f / 3.f)) * z;
                } else if (st4 == 1) {
                    k2 = z;
                    g_ws[j2] = wcur + h * (z - k1 * (1.f / 3.f));
                } else if (st4 == 2) {
                    k3 = z;
                    g_ws[j2] = wcur + h * (k1 - k2 + z);
                } else {
                    wcur += h * 0.125f * (k1 + 3.f * (k2 + k3) + z);
                    g_w[j2] = wcur;
                }
            }
        }
        if (stage != 4 * (T_STEPS - 1) - 1) {
            tgt += NB_ODE;
            gridsync(tgt);
        }
    }
}

// ---------------- xw: z[n] = dis[n] * (x_last[n] @ W_T), stored fp16 ----------------
__global__ void xw_kernel(const float* __restrict__ xlast, int n) {
    __shared__ float Ws[64 * 64];
    __shared__ float xs[64 * 64];
    int n0 = blockIdx.x * 64;
    for (int i = threadIdx.x; i < 4096; i += 256) Ws[i] = g_w[i];
    for (int i = threadIdx.x; i < 4096; i += 256) {
        int r = i >> 6, c = i & 63, nn = n0 + r;
        xs[i] = (nn < n) ? xlast[(size_t)nn * 64 + c] : 0.f;
    }
    __syncthreads();
    int tx = threadIdx.x & 15, ty = threadIdx.x >> 4;
    float acc[4][4] = {};
#pragma unroll 4
    for (int k = 0; k < 64; ++k) {
        float4 b = *(const float4*)&Ws[k * 64 + tx * 4];
#pragma unroll
        for (int i = 0; i < 4; ++i) {
            float a = xs[(ty * 4 + i) * 64 + k];
            acc[i][0] += a * b.x; acc[i][1] += a * b.y;
            acc[i][2] += a * b.z; acc[i][3] += a * b.w;
        }
    }
#pragma unroll
    for (int i = 0; i < 4; ++i) {
        int nn = n0 + ty * 4 + i;
        if (nn < n) {
            float dn = g_dis[nn];
            __half2 h0 = __floats2half2_rn(dn * acc[i][0], dn * acc[i][1]);
            __half2 h1 = __floats2half2_rn(dn * acc[i][2], dn * acc[i][3]);
            uint2 pk = make_uint2(*(unsigned*)&h0, *(unsigned*)&h1);
            *(uint2*)&g_zh[(size_t)nn * 32 + tx * 2] = pk;
        }
    }
}

// ---------------- gather: acc[c] = dis[c] * (z[c] + sum_in z[src]) ----------------
// warp per node; fp16 z rows (one half2 per lane = full 64-col row per warp)
__global__ void gather_kernel(int n) {
    int gw   = (blockIdx.x * 256 + threadIdx.x) >> 5;
    int lane = threadIdx.x & 31;
    if (gw >= n) return;
    int k0 = g_base[gw], k1 = g_base[gw + 1];
    float2 s = __half22float2(g_zh[(size_t)gw * 32 + lane]);   // self-loop term
    for (int kb = k0; kb < k1; kb += 32) {
        int m = k1 - kb; if (m > 32) m = 32;
        int rl = (lane < m) ? __ldg(&g_src[kb + lane]) : 0;
#pragma unroll 4
        for (int j = 0; j < m; ++j) {
            int r = __shfl_sync(0xffffffffu, rl, j);
            float2 v = __half22float2(g_zh[(size_t)r * 32 + lane]);
            s.x += v.x; s.y += v.y;
        }
    }
    float dc = g_dis[gw];
    float* acc = (float*)g_acc4;
    *(float2*)&acc[(size_t)gw * 64 + 2 * lane] = make_float2(dc * s.x, dc * s.y);
}

// ---------------- hA/hB fused: h = relu(acc); hA = h@W[0:64]+b1; hB = h@W[64:128] ----------------
__global__ void hab_kernel(const float* __restrict__ mw1, const float* __restrict__ mb1,
                           int n) {
    __shared__ float Ws[64 * 64];
    __shared__ float xs[64 * 64];
    const float* ga = (const float*)g_acc4;
    int n0 = blockIdx.x * 64;
    for (int i = threadIdx.x; i < 4096; i += 256) {
        int r = i >> 6, c = i & 63, nn = n0 + r;
        xs[i] = (nn < n) ? fmaxf(ga[nn * 64 + c], 0.f) : 0.f;
    }
    int tx = threadIdx.x & 15, ty = threadIdx.x >> 4;
#pragma unroll
    for (int sel = 0; sel < 2; ++sel) {
        __syncthreads();
        for (int i = threadIdx.x; i < 4096; i += 256) Ws[i] = mw1[sel * 4096 + i];
        __syncthreads();
        float acc[4][4] = {};
#pragma unroll 4
        for (int k = 0; k < 64; ++k) {
            float4 b = *(const float4*)&Ws[k * 64 + tx * 4];
#pragma unroll
            for (int i = 0; i < 4; ++i) {
                float a = xs[(ty * 4 + i) * 64 + k];
                acc[i][0] += a * b.x; acc[i][1] += a * b.y;
                acc[i][2] += a * b.z; acc[i][3] += a * b.w;
            }
        }
        float4 bb = make_float4(0.f, 0.f, 0.f, 0.f);
        if (sel == 0) {
            bb.x = mb1[tx * 4 + 0]; bb.y = mb1[tx * 4 + 1];
            bb.z = mb1[tx * 4 + 2]; bb.w = mb1[tx * 4 + 3];
        }
        __half2* out = sel ? g_hBh : g_hAh;
#pragma unroll
        for (int i = 0; i < 4; ++i) {
            int nn = n0 + ty * 4 + i;
            if (nn < n) {
                __half2 h0 = __floats2half2_rn(acc[i][0] + bb.x, acc[i][1] + bb.y);
                __half2 h1 = __floats2half2_rn(acc[i][2] + bb.z, acc[i][3] + bb.w);
                uint2 pk = make_uint2(*(unsigned*)&h0, *(unsigned*)&h1);
                *(uint2*)&out[(size_t)nn * 32 + tx * 2] = pk;
            }
        }
    }
}

// ---------------- edge MLP: out[e] = relu(hA[r]+hB[c]+ea@C) . w2 + b2 ----------------
// block = 256 threads / 64 edges; lane owns columns j=2*lane, 2*lane+1
__global__ __launch_bounds__(256)
void edge_kernel(const float* __restrict__ ea, const int* __restrict__ ei,
                 const float* __restrict__ mw1, const float* __restrict__ w2,
                 const float* __restrict__ b2, float* __restrict__ out, int e) {
    __shared__ float4 sea[EPB * 4];
    __shared__ int   sr[EPB], sc[EPB];
    __shared__ float sout[EPB];
    const int tid  = threadIdx.x;
    const int lane = tid & 31;
    const int warp = tid >> 5;
    const int e0   = blockIdx.x * EPB;
    const int valid = (e - e0 < EPB) ? (e - e0) : EPB;

    // edge-invariant operands -> registers (once per block); pair layout j=2*lane,2*lane+1
    float c0[16], c1[16];
#pragma unroll
    for (int f = 0; f < 16; ++f) {
        float2 cc = *(const float2*)&mw1[(128 + f) * 64 + 2 * lane];
        c0[f] = cc.x; c1[f] = cc.y;
    }
    const float2 w2p = *(const float2*)&w2[2 * lane];
    const float  bb  = __ldg(&b2[0]);

    // stage ea (float4) + indices
    if (tid < valid * 4) sea[tid] = ((const float4*)(ea + (size_t)e0 * 16))[tid];
    if (tid < valid)                sr[tid]       = __ldg(&ei[e0 + tid]);
    else if (tid >= EPB && tid < EPB + valid) sc[tid - EPB] = __ldg(&ei[e + e0 + (tid - EPB)]);
    __syncthreads();

#pragma unroll
    for (int it = 0; it < 8; ++it) {
        int le = warp * 8 + it;
        if (le < valid) {
            int r = sr[le], c = sc[le];
            float2 fa = __half22float2(g_hAh[(size_t)r * 32 + lane]);
            float2 fb = __half22float2(g_hBh[(size_t)c * 32 + lane]);
            float s0 = fa.x + fb.x;
            float s1 = fa.y + fb.y;
#pragma unroll
            for (int q = 0; q < 4; ++q) {
                float4 a = sea[le * 4 + q];
                s0 += a.x * c0[4 * q] + a.y * c0[4 * q + 1] + a.z * c0[4 * q + 2] + a.w * c0[4 * q + 3];
                s1 += a.x * c1[4 * q] + a.y * c1[4 * q + 1] + a.z * c1[4 * q + 2] + a.w * c1[4 * q + 3];
            }
            float p = fmaxf(s0, 0.f) * w2p.x + fmaxf(s1, 0.f) * w2p.y;
#pragma unroll
            for (int o = 16; o; o >>= 1) p += __shfl_xor_sync(0xffffffffu, p, o);
            if (lane == 0) sout[le] = p + bb;
        }
    }
    __syncthreads();
    if (tid < valid) out[e0 + tid] = sout[tid];
}

// ---------------- launcher ----------------
extern "C" void kernel_launch(void* const* d_in, const int* in_sizes, int n_in,
                              void* d_out, int out_size) {
    const float* x_seq = (const float*)d_in[0];
    const float* ea    = (const float*)d_in[1];
    const float* iw    = (const float*)d_in[2];
    const float* W1    = (const float*)d_in[3];
    const float* b1o   = (const float*)d_in[4];
    const float* W2    = (const float*)d_in[5];
    const float* b2o   = (const float*)d_in[6];
    const float* mw1   = (const float*)d_in[7];
    const float* mb1   = (const float*)d_in[8];
    const float* mw2   = (const float*)d_in[9];
    const float* mb2   = (const float*)d_in[10];
    const int*   ei    = (const int*)d_in[11];
    float* out = (float*)d_out;

    const int n = NN;
    const int e = EE;
    const float* xlast = x_seq + (size_t)(T_STEPS - 1) * n * 64;
    const float h = 1.0f / (float)(T_STEPS - 1);

    cudaFuncSetAttribute(ode_persist, cudaFuncAttributeMaxDynamicSharedMemorySize,
                         ODE_SMEM_FLOATS * 4);

    // init + transposes + ODE first (keeps ode_persist early for ncu attribution)
    init_kernel<<<(n + 255) / 256, 256>>>(iw, n);
    {
        float* w1t; cudaGetSymbolAddress((void**)&w1t, g_W1t);
        float* w2t; cudaGetSymbolAddress((void**)&w2t, g_W2t);
        dim3 t1g(BN / 32, FLAT / 32);
        transpose_kernel<<<t1g, dim3(32, 8)>>>(W1, w1t, FLAT, BN);
        dim3 t2g(FLAT / 32, BN / 32);
        transpose_kernel<<<t2g, dim3(32, 8)>>>(W2, w2t, BN, FLAT);
    }
    ode_persist<<<NB_ODE, 1024, ODE_SMEM_FLOATS * 4>>>(b1o, b2o, h);

    // CSR build + normalization (independent of ODE result)
    count_kernel<<<(e + 255) / 256, 256>>>(ei, e);
    dis_kernel<<<(n + 255) / 256, 256>>>(n);
    scan1_kernel<<<NB_SCAN, 1024>>>(n);
    scan2_kernel<<<1, 128>>>(NB_SCAN);
    scan3_kernel<<<NB_SCAN, 1024>>>(n);
    place_kernel<<<(e + 255) / 256, 256>>>(ei, e);

    // GCN: dense part, then atomic-free gather (fp16 z table)
    xw_kernel<<<(n + 63) / 64, 256>>>(xlast, n);
    gather_kernel<<<(n * 32 + 255) / 256, 256>>>(n);

    // node-side halves of the edge MLP first layer (fp16 tables)
    hab_kernel<<<(n + 63) / 64, 256>>>(mw1, mb1, n);

    // per-edge MLP
    edge_kernel<<<(e + EPB - 1) / EPB, 256>>>(ea, ei, mw1, mw2, mb2, out, e);
}

// round 7
// speedup vs baseline: 2.0990x; 1.1260x over previous
#include <cuda_runtime.h>
#include <cuda_fp16.h>

// Problem constants (fixed by the dataset)
#define T_STEPS 8
#define NN      100000
#define EE      1600000
#define FLAT    4096    // 64*64
#define BN      1024    // bottleneck
#define NB_ODE  128     // persistent ODE grid (1 block/SM, co-resident)
#define NB_SCAN 98      // ceil(NN/1024)
#define EPB     64      // edges per block in edge_kernel

// ---------------- device scratch (no allocs allowed) ----------------
__device__ float  g_w[FLAT];
__device__ float  g_ws[FLAT];
__device__ float  g_t[BN];
__device__ float  g_W1t[BN * FLAT];   // transposed: row j (1024 rows) x k (4096)
__device__ float  g_W2t[FLAT * BN];   // transposed: row j (4096 rows) x k (1024)
__device__ unsigned g_barcnt;
__device__ float  g_dis[NN];
__device__ int    g_cnt[NN];        // in-degree (no self)
__device__ int    g_base[NN + 1];   // CSR row offsets (by destination)
__device__ int    g_cur[NN];        // placement cursors
__device__ int    g_src[EE];        // CSR: source node per in-edge
__device__ int    g_bsum[NB_SCAN];
__device__ int    g_boff[NB_SCAN];
__device__ __align__(16) __half2 g_zh[NN * 32];   // dis[n]*(x W_T)  fp16 [N,64]
__device__ __align__(16) __half2 g_hAh[NN * 32];  // h@A+b1 fp16      [N,64]
__device__ __align__(16) __half2 g_hBh[NN * 32];  // h@B    fp16      [N,64]

// ---------------- init: copy w0, zero counters, reset barrier ----------------
__global__ void init_kernel(const float* __restrict__ iw, int n) {
    int i = blockIdx.x * 256 + threadIdx.x;
    if (i == 0) g_barcnt = 0u;
    if (i < FLAT) g_w[i] = iw[i];
    if (i < n)    g_cnt[i] = 0;
}

// ---------------- in-degree count ----------------
__global__ void count_kernel(const int* __restrict__ ei, int e) {
    int i = blockIdx.x * 256 + threadIdx.x;
    if (i < e) atomicAdd(&g_cnt[ei[e + i]], 1);
}

// ---------------- dis = rsqrt(deg), deg = cnt + 1 (self loop) ----------------
__global__ void dis_kernel(int n) {
    int i = blockIdx.x * 256 + threadIdx.x;
    if (i < n) g_dis[i] = rsqrtf(1.0f + (float)g_cnt[i]);
}

// ---------------- CSR offset scan (3 small kernels) ----------------
__global__ void scan1_kernel(int n) {            // block sums
    __shared__ int sm_[1024];
    int i = blockIdx.x * 1024 + threadIdx.x;
    sm_[threadIdx.x] = (i < n) ? g_cnt[i] : 0;
    __syncthreads();
#pragma unroll
    for (int o = 512; o; o >>= 1) {
        if (threadIdx.x < o) sm_[threadIdx.x] += sm_[threadIdx.x + o];
        __syncthreads();
    }
    if (threadIdx.x == 0) g_bsum[blockIdx.x] = sm_[0];
}

__global__ void scan2_kernel(int nb) {           // serial scan of block sums
    __shared__ int sb[NB_SCAN];
    if (threadIdx.x < nb) sb[threadIdx.x] = g_bsum[threadIdx.x];
    __syncthreads();
    if (threadIdx.x == 0) {
        int run = 0;
        for (int b = 0; b < nb; ++b) { g_boff[b] = run; run += sb[b]; }
        g_base[NN] = run;            // == EE
    }
}

__global__ void scan3_kernel(int n) {            // in-block exclusive scan + offset
    __shared__ int sm_[1024];
    int i = blockIdx.x * 1024 + threadIdx.x;
    int v = (i < n) ? g_cnt[i] : 0;
    sm_[threadIdx.x] = v;
    __syncthreads();
#pragma unroll
    for (int o = 1; o < 1024; o <<= 1) {         // Hillis-Steele inclusive
        int t = (threadIdx.x >= o) ? sm_[threadIdx.x - o] : 0;
        __syncthreads();
        sm_[threadIdx.x] += t;
        __syncthreads();
    }
    if (i < n) {
        int excl = sm_[threadIdx.x] - v + g_boff[blockIdx.x];
        g_base[i] = excl;
        g_cur[i]  = excl;
    }
}

// ---------------- CSR placement ----------------
__global__ void place_kernel(const int* __restrict__ ei, int e) {
    int i = blockIdx.x * 256 + threadIdx.x;
    if (i < e) {
        int c = ei[e + i];
        int p = atomicAdd(&g_cur[c], 1);
        g_src[p] = ei[i];
    }
}

// ---------------- 32x32 tiled transpose: dst[C][R] = src[R][C]^T ----------------
__global__ void transpose_kernel(const float* __restrict__ src, float* __restrict__ dst,
                                 int R, int C) {
    __shared__ float tile[32][33];
    int bx = blockIdx.x * 32, by = blockIdx.y * 32;
    int x = bx + threadIdx.x;
#pragma unroll
    for (int i = 0; i < 32; i += 8) {
        int y = by + threadIdx.y + i;
        tile[threadIdx.y + i][threadIdx.x] = src[(size_t)y * C + x];
    }
    __syncthreads();
    int x2 = by + threadIdx.x;
#pragma unroll
    for (int i = 0; i < 32; i += 8) {
        int y2 = bx + threadIdx.y + i;
        dst[(size_t)y2 * R + x2] = tile[threadIdx.x][threadIdx.y + i];
    }
}

// ---------------- fast grid barrier: monotonic counter, acquire/release ----------------
__device__ __forceinline__ void gridsync(unsigned target) {
    __syncthreads();
    if (threadIdx.x == 0) {
        asm volatile("red.add.release.gpu.u32 [%0], %1;"
                     :: "l"(&g_barcnt), "r"(1u) : "memory");
        unsigned v;
        do {
            asm volatile("ld.acquire.gpu.u32 %0, [%1];"
                         : "=r"(v) : "l"(&g_barcnt) : "memory");
        } while (v < target);
    }
    __syncthreads();
}

// ---------------- persistent ODE (unchanged) ----------------
#define ODE_SMEM_FLOATS (32768 + 4096 + 1024 + 32)

__global__ __launch_bounds__(1024, 1)
void ode_persist(const float* __restrict__ b1, const float* __restrict__ b2, float h) {
    extern __shared__ float sm[];
    float* sW1 = sm;
    float* sw  = sm + 32768;
    float* st  = sm + 32768 + 4096;
    float* red = sm + 32768 + 4096 + 1024;   // [8 groups][4 warps]

    const int tid  = threadIdx.x;
    const int b    = blockIdx.x;
    const int lane = tid & 31;
    const int wid  = tid >> 5;
    const int grp  = tid >> 7;
    const int tin  = tid & 127;
    const int wgrp = tin >> 5;

    {
        const float4* src = (const float4*)(g_W1t + ((size_t)b * 8) * 4096);
        float4* dst = (float4*)sW1;
#pragma unroll
        for (int i = 0; i < 8; ++i) dst[tid + 1024 * i] = src[tid + 1024 * i];
    }
    float4 w2r[8];
    {
        const float4* src = (const float4*)(g_W2t + ((size_t)(b * 32 + wid)) * 1024);
#pragma unroll
        for (int i = 0; i < 8; ++i) w2r[i] = src[lane + 32 * i];
    }
    const int   j2  = b * 32 + wid;
    const float b2j = b2[j2];
    float wcur = g_w[j2];
    float k1 = 0.f, k2 = 0.f, k3 = 0.f;
    unsigned tgt = 0;
    __syncthreads();

    for (int stage = 0; stage < 4 * (T_STEPS - 1); ++stage) {
        const int st4 = stage & 3;
        {
            const float4* win = (const float4*)(st4 == 0 ? g_w : g_ws);
            ((float4*)sw)[tid] = __ldcg(win + tid);
        }
        __syncthreads();

        {
            const float4* wrow = (const float4*)(sW1 + (size_t)grp * 4096);
            const float4* sw4  = (const float4*)sw;
            float s = 0.f;
#pragma unroll
            for (int i = 0; i < 8; ++i) {
                float4 a = wrow[tin + 128 * i];
                float4 v = sw4[tin + 128 * i];
                s += a.x * v.x + a.y * v.y + a.z * v.z + a.w * v.w;
            }
#pragma unroll
            for (int o = 16; o; o >>= 1) s += __shfl_xor_sync(0xffffffffu, s, o);
            if (lane == 0) red[grp * 4 + wgrp] = s;
        }
        __syncthreads();
        if (tid < 8) {
            float tot = red[tid * 4] + red[tid * 4 + 1] + red[tid * 4 + 2] + red[tid * 4 + 3];
            g_t[b * 8 + tid] = tanhf(tot + b1[b * 8 + tid]);
        }
        tgt += NB_ODE;
        gridsync(tgt);

        if (tid < 256) ((float4*)st)[tid] = __ldcg(((const float4*)g_t) + tid);
        __syncthreads();
        {
            const float4* st4p = (const float4*)st;
            float s = 0.f;
#pragma unroll
            for (int i = 0; i < 8; ++i) {
                float4 a = w2r[i];
                float4 v = st4p[lane + 32 * i];
                s += a.x * v.x + a.y * v.y + a.z * v.z + a.w * v.w;
            }
#pragma unroll
            for (int o = 16; o; o >>= 1) s += __shfl_xor_sync(0xffffffffu, s, o);
            if (lane == 0) {
                float z = s + b2j;
                if (st4 == 0) {
                    k1 = z;
                    g_ws[j2] = wcur + (h * (1.f / 3.f)) * z;
                } else if (st4 == 1) {
                    k2 = z;
                    g_ws[j2] = wcur + h * (z - k1 * (1.f / 3.f));
                } else if (st4 == 2) {
                    k3 = z;
                    g_ws[j2] = wcur + h * (k1 - k2 + z);
                } else {
                    wcur += h * 0.125f * (k1 + 3.f * (k2 + k3) + z);
                    g_w[j2] = wcur;
                }
            }
        }
        if (stage != 4 * (T_STEPS - 1) - 1) {
            tgt += NB_ODE;
            gridsync(tgt);
        }
    }
}

// ---------------- xw: z[n] = dis[n] * (x_last[n] @ W_T), stored fp16 ----------------
__global__ void xw_kernel(const float* __restrict__ xlast, int n) {
    __shared__ float Ws[64 * 64];
    __shared__ float xs[64 * 64];
    int n0 = blockIdx.x * 64;
    for (int i = threadIdx.x; i < 4096; i += 256) Ws[i] = g_w[i];
    for (int i = threadIdx.x; i < 4096; i += 256) {
        int r = i >> 6, c = i & 63, nn = n0 + r;
        xs[i] = (nn < n) ? xlast[(size_t)nn * 64 + c] : 0.f;
    }
    __syncthreads();
    int tx = threadIdx.x & 15, ty = threadIdx.x >> 4;
    float acc[4][4] = {};
#pragma unroll 4
    for (int k = 0; k < 64; ++k) {
        float4 b = *(const float4*)&Ws[k * 64 + tx * 4];
#pragma unroll
        for (int i = 0; i < 4; ++i) {
            float a = xs[(ty * 4 + i) * 64 + k];
            acc[i][0] += a * b.x; acc[i][1] += a * b.y;
            acc[i][2] += a * b.z; acc[i][3] += a * b.w;
        }
    }
#pragma unroll
    for (int i = 0; i < 4; ++i) {
        int nn = n0 + ty * 4 + i;
        if (nn < n) {
            float dn = g_dis[nn];
            __half2 h0 = __floats2half2_rn(dn * acc[i][0], dn * acc[i][1]);
            __half2 h1 = __floats2half2_rn(dn * acc[i][2], dn * acc[i][3]);
            uint2 pk = make_uint2(*(unsigned*)&h0, *(unsigned*)&h1);
            *(uint2*)&g_zh[(size_t)nn * 32 + tx * 2] = pk;
        }
    }
}

// ---------------- fused gather + hA/hB ----------------
// block = 256 threads / 64 nodes. Phase 1: warp-per-node CSR gather ->
// relu'd rows directly into the GEMM smem tile. Phase 2: two 64x64 GEMMs.
__global__ __launch_bounds__(256)
void gatherhab_kernel(const float* __restrict__ mw1, const float* __restrict__ mb1,
                      int n) {
    __shared__ float Ws[64 * 64];
    __shared__ float xs[64 * 64];
    const int tid  = threadIdx.x;
    const int lane = tid & 31;
    const int warp = tid >> 5;
    const int n0   = blockIdx.x * 64;

    // phase 1: each warp gathers 8 nodes
#pragma unroll 1
    for (int i = 0; i < 8; ++i) {
        int local = warp * 8 + i;
        int nn = n0 + local;
        float2 s = make_float2(0.f, 0.f);
        float dc = 0.f;
        if (nn < n) {
            int k0 = g_base[nn], k1 = g_base[nn + 1];
            s = __half22float2(g_zh[(size_t)nn * 32 + lane]);   // self-loop term
            for (int kb = k0; kb < k1; kb += 32) {
                int m = k1 - kb; if (m > 32) m = 32;
                int rl = (lane < m) ? __ldg(&g_src[kb + lane]) : 0;
#pragma unroll 4
                for (int j = 0; j < m; ++j) {
                    int r = __shfl_sync(0xffffffffu, rl, j);
                    float2 v = __half22float2(g_zh[(size_t)r * 32 + lane]);
                    s.x += v.x; s.y += v.y;
                }
            }
            dc = g_dis[nn];
        }
        *(float2*)&xs[local * 64 + 2 * lane] =
            make_float2(fmaxf(dc * s.x, 0.f), fmaxf(dc * s.y, 0.f));
    }
    __syncthreads();

    // phase 2: hA = relu-tile @ W[0:64] + b1 ; hB = relu-tile @ W[64:128]
    int tx = tid & 15, ty = tid >> 4;
#pragma unroll
    for (int sel = 0; sel < 2; ++sel) {
        if (sel) __syncthreads();
        for (int i = tid; i < 4096; i += 256) Ws[i] = mw1[sel * 4096 + i];
        __syncthreads();
        float acc[4][4] = {};
#pragma unroll 4
        for (int k = 0; k < 64; ++k) {
            float4 b = *(const float4*)&Ws[k * 64 + tx * 4];
#pragma unroll
            for (int i = 0; i < 4; ++i) {
                float a = xs[(ty * 4 + i) * 64 + k];
                acc[i][0] += a * b.x; acc[i][1] += a * b.y;
                acc[i][2] += a * b.z; acc[i][3] += a * b.w;
            }
        }
        float4 bb = make_float4(0.f, 0.f, 0.f, 0.f);
        if (sel == 0) {
            bb.x = mb1[tx * 4 + 0]; bb.y = mb1[tx * 4 + 1];
            bb.z = mb1[tx * 4 + 2]; bb.w = mb1[tx * 4 + 3];
        }
        __half2* out = sel ? g_hBh : g_hAh;
#pragma unroll
        for (int i = 0; i < 4; ++i) {
            int nn = n0 + ty * 4 + i;
            if (nn < n) {
                __half2 h0 = __floats2half2_rn(acc[i][0] + bb.x, acc[i][1] + bb.y);
                __half2 h1 = __floats2half2_rn(acc[i][2] + bb.z, acc[i][3] + bb.w);
                uint2 pk = make_uint2(*(unsigned*)&h0, *(unsigned*)&h1);
                *(uint2*)&out[(size_t)nn * 32 + tx * 2] = pk;
            }
        }
    }
}

// ---------------- edge MLP: out[e] = relu(hA[r]+hB[c]+ea@C) . w2 + b2 ----------------
// block = 256 threads / 64 edges; lane owns columns j=2*lane, 2*lane+1
__global__ __launch_bounds__(256)
void edge_kernel(const float* __restrict__ ea, const int* __restrict__ ei,
                 const float* __restrict__ mw1, const float* __restrict__ w2,
                 const float* __restrict__ b2, float* __restrict__ out, int e) {
    __shared__ float4 sea[EPB * 4];
    __shared__ int   sr[EPB], sc[EPB];
    __shared__ float sout[EPB];
    const int tid  = threadIdx.x;
    const int lane = tid & 31;
    const int warp = tid >> 5;
    const int e0   = blockIdx.x * EPB;
    const int valid = (e - e0 < EPB) ? (e - e0) : EPB;

    // edge-invariant operands -> registers (once per block)
    float c0[16], c1[16];
#pragma unroll
    for (int f = 0; f < 16; ++f) {
        float2 cc = *(const float2*)&mw1[(128 + f) * 64 + 2 * lane];
        c0[f] = cc.x; c1[f] = cc.y;
    }
    const float2 w2p = *(const float2*)&w2[2 * lane];
    const float  bb  = __ldg(&b2[0]);

    // stage ea (float4) + indices
    if (tid < valid * 4) sea[tid] = ((const float4*)(ea + (size_t)e0 * 16))[tid];
    if (tid < valid)                sr[tid]       = __ldg(&ei[e0 + tid]);
    else if (tid >= EPB && tid < EPB + valid) sc[tid - EPB] = __ldg(&ei[e + e0 + (tid - EPB)]);
    __syncthreads();

    if (valid == EPB) {
        // fast path: branch-free, 2-edge software pipeline
#pragma unroll 2
        for (int it = 0; it < 8; it += 2) {
            int le0 = warp * 8 + it, le1 = le0 + 1;
            int r0 = sr[le0], cc0 = sc[le0];
            int r1 = sr[le1], cc1 = sc[le1];
            float2 fa0 = __half22float2(g_hAh[(size_t)r0 * 32 + lane]);
            float2 fb0 = __half22float2(g_hBh[(size_t)cc0 * 32 + lane]);
            float2 fa1 = __half22float2(g_hAh[(size_t)r1 * 32 + lane]);
            float2 fb1 = __half22float2(g_hBh[(size_t)cc1 * 32 + lane]);
            float s00 = fa0.x + fb0.x, s01 = fa0.y + fb0.y;
            float s10 = fa1.x + fb1.x, s11 = fa1.y + fb1.y;
#pragma unroll
            for (int q = 0; q < 4; ++q) {
                float4 a0 = sea[le0 * 4 + q];
                float4 a1 = sea[le1 * 4 + q];
                s00 += a0.x * c0[4 * q] + a0.y * c0[4 * q + 1] + a0.z * c0[4 * q + 2] + a0.w * c0[4 * q + 3];
                s01 += a0.x * c1[4 * q] + a0.y * c1[4 * q + 1] + a0.z * c1[4 * q + 2] + a0.w * c1[4 * q + 3];
                s10 += a1.x * c0[4 * q] + a1.y * c0[4 * q + 1] + a1.z * c0[4 * q + 2] + a1.w * c0[4 * q + 3];
                s11 += a1.x * c1[4 * q] + a1.y * c1[4 * q + 1] + a1.z * c1[4 * q + 2] + a1.w * c1[4 * q + 3];
            }
            float p0 = fmaxf(s00, 0.f) * w2p.x + fmaxf(s01, 0.f) * w2p.y;
            float p1 = fmaxf(s10, 0.f) * w2p.x + fmaxf(s11, 0.f) * w2p.y;
#pragma unroll
            for (int o = 16; o; o >>= 1) {
                p0 += __shfl_xor_sync(0xffffffffu, p0, o);
                p1 += __shfl_xor_sync(0xffffffffu, p1, o);
            }
            if (lane == 0) { sout[le0] = p0 + bb; sout[le1] = p1 + bb; }
        }
    } else {
        for (int it = 0; it < 8; ++it) {
            int le = warp * 8 + it;
            if (le < valid) {
                int r = sr[le], c = sc[le];
                float2 fa = __half22float2(g_hAh[(size_t)r * 32 + lane]);
                float2 fb = __half22float2(g_hBh[(size_t)c * 32 + lane]);
                float s0 = fa.x + fb.x;
                float s1 = fa.y + fb.y;
#pragma unroll
                for (int q = 0; q < 4; ++q) {
                    float4 a = sea[le * 4 + q];
                    s0 += a.x * c0[4 * q] + a.y * c0[4 * q + 1] + a.z * c0[4 * q + 2] + a.w * c0[4 * q + 3];
                    s1 += a.x * c1[4 * q] + a.y * c1[4 * q + 1] + a.z * c1[4 * q + 2] + a.w * c1[4 * q + 3];
                }
                float p = fmaxf(s0, 0.f) * w2p.x + fmaxf(s1, 0.f) * w2p.y;
#pragma unroll
                for (int o = 16; o; o >>= 1) p += __shfl_xor_sync(0xffffffffu, p, o);
                if (lane == 0) sout[le] = p + bb;
            }
        }
    }
    __syncthreads();
    if (tid < valid) out[e0 + tid] = sout[tid];
}

// ---------------- launcher ----------------
extern "C" void kernel_launch(void* const* d_in, const int* in_sizes, int n_in,
                              void* d_out, int out_size) {
    const float* x_seq = (const float*)d_in[0];
    const float* ea    = (const float*)d_in[1];
    const float* iw    = (const float*)d_in[2];
    const float* W1    = (const float*)d_in[3];
    const float* b1o   = (const float*)d_in[4];
    const float* W2    = (const float*)d_in[5];
    const float* b2o   = (const float*)d_in[6];
    const float* mw1   = (const float*)d_in[7];
    const float* mb1   = (const float*)d_in[8];
    const float* mw2   = (const float*)d_in[9];
    const float* mb2   = (const float*)d_in[10];
    const int*   ei    = (const int*)d_in[11];
    float* out = (float*)d_out;

    const int n = NN;
    const int e = EE;
    const float* xlast = x_seq + (size_t)(T_STEPS - 1) * n * 64;
    const float h = 1.0f / (float)(T_STEPS - 1);

    cudaFuncSetAttribute(ode_persist, cudaFuncAttributeMaxDynamicSharedMemorySize,
                         ODE_SMEM_FLOATS * 4);

    // fork-join: stream B runs the CSR scan/placement chain concurrently with
    // the transposes + persistent ODE on the main stream.
    cudaStream_t sB;
    cudaStreamCreateWithFlags(&sB, cudaStreamNonBlocking);
    cudaEvent_t evFork, evJoin;
    cudaEventCreateWithFlags(&evFork, cudaEventDisableTiming);
    cudaEventCreateWithFlags(&evJoin, cudaEventDisableTiming);

    // main stream: init + count (prerequisites for both branches)
    init_kernel<<<(n + 255) / 256, 256>>>(iw, n);
    count_kernel<<<(e + 255) / 256, 256>>>(ei, e);
    cudaEventRecord(evFork, 0);
    cudaStreamWaitEvent(sB, evFork, 0);

    // stream B: scan + place (needs only g_cnt)
    scan1_kernel<<<NB_SCAN, 1024, 0, sB>>>(n);
    scan2_kernel<<<1, 128, 0, sB>>>(NB_SCAN);
    scan3_kernel<<<NB_SCAN, 1024, 0, sB>>>(n);
    place_kernel<<<(e + 255) / 256, 256, 0, sB>>>(ei, e);
    cudaEventRecord(evJoin, sB);

    // main stream: dis, transposes, ODE, xw
    dis_kernel<<<(n + 255) / 256, 256>>>(n);
    {
        float* w1t; cudaGetSymbolAddress((void**)&w1t, g_W1t);
        float* w2t; cudaGetSymbolAddress((void**)&w2t, g_W2t);
        dim3 t1g(BN / 32, FLAT / 32);
        transpose_kernel<<<t1g, dim3(32, 8)>>>(W1, w1t, FLAT, BN);
        dim3 t2g(FLAT / 32, BN / 32);
        transpose_kernel<<<t2g, dim3(32, 8)>>>(W2, w2t, BN, FLAT);
    }
    ode_persist<<<NB_ODE, 1024, ODE_SMEM_FLOATS * 4>>>(b1o, b2o, h);
    xw_kernel<<<(n + 63) / 64, 256>>>(xlast, n);

    // join: gather/hab and edge need the CSR from stream B
    cudaStreamWaitEvent(0, evJoin, 0);
    gatherhab_kernel<<<(n + 63) / 64, 256>>>(mw1, mb1, n);
    edge_kernel<<<(e + EPB - 1) / EPB, 256>>>(ea, ei, mw1, mw2, mb2, out, e);

    cudaEventDestroy(evFork);
    cudaEventDestroy(evJoin);
    cudaStreamDestroy(sB);
}